// round 14
// baseline (speedup 1.0000x reference)
#include <cuda_runtime.h>
#include <cuda_bf16.h>
#include <math.h>
#include <stdint.h>

// ---------------------------------------------------------------------------
// Problem constants
// ---------------------------------------------------------------------------
#define L_LAYERS 6
#define V_VOCAB  512
#define D_MODEL  768
#define P_PROJ   768
#define N_HEADS  12
#define HD       64
#define FF_DIM   3072
#define B_BATCH  8
#define T_SEQ    1024
#define ROWS     (B_BATCH * T_SEQ)   // 8192
#define LN_EPS   1e-5f
#define NQKV     (3 * P_PROJ)        // 2304

// ---------------------------------------------------------------------------
// Scratch (device globals: allocation-free rule)
// ---------------------------------------------------------------------------
__device__ float g_x   [ROWS * D_MODEL];          // residual stream (fp32)
__device__ float g_part[3 * ROWS * D_MODEL];      // split-K partials (x3)

__device__ __nv_bfloat16 g_qkv_hi[ROWS * NQKV];   // fused q|k|v split bf16
__device__ __nv_bfloat16 g_qkv_lo[ROWS * NQKV];

__device__ __nv_bfloat16 g_h_hi [ROWS * D_MODEL];
__device__ __nv_bfloat16 g_h_lo [ROWS * D_MODEL];
__device__ __nv_bfloat16 g_y_hi [ROWS * P_PROJ];
__device__ __nv_bfloat16 g_y_lo [ROWS * P_PROJ];
__device__ __nv_bfloat16 g_m1_hi[ROWS * FF_DIM];
__device__ __nv_bfloat16 g_m1_lo[ROWS * FF_DIM];

// split weights ([K,N] row-major, as hgemm consumes them)
__device__ __nv_bfloat16 g_wqkv_hi[L_LAYERS * D_MODEL * NQKV];
__device__ __nv_bfloat16 g_wqkv_lo[L_LAYERS * D_MODEL * NQKV];
__device__ float         g_bqkv  [L_LAYERS * NQKV];
__device__ __nv_bfloat16 g_wo_hi[L_LAYERS * P_PROJ * D_MODEL];
__device__ __nv_bfloat16 g_wo_lo[L_LAYERS * P_PROJ * D_MODEL];
__device__ __nv_bfloat16 g_w1_hi[L_LAYERS * D_MODEL * FF_DIM];
__device__ __nv_bfloat16 g_w1_lo[L_LAYERS * D_MODEL * FF_DIM];
__device__ __nv_bfloat16 g_w2_hi[L_LAYERS * FF_DIM * D_MODEL];
__device__ __nv_bfloat16 g_w2_lo[L_LAYERS * FF_DIM * D_MODEL];
__device__ __nv_bfloat16 g_wout_hi[D_MODEL * V_VOCAB];
__device__ __nv_bfloat16 g_wout_lo[D_MODEL * V_VOCAB];

// ---------------------------------------------------------------------------
// Small helpers
// ---------------------------------------------------------------------------
__device__ __forceinline__ uint32_t smem_u32(const void* p) {
    return (uint32_t)__cvta_generic_to_shared(p);
}
__device__ __forceinline__ void cp_async16(uint32_t dst, const void* src) {
    asm volatile("cp.async.cg.shared.global [%0], [%1], 16;" :: "r"(dst), "l"(src));
}
__device__ __forceinline__ void cp_commit() {
    asm volatile("cp.async.commit_group;");
}
__device__ __forceinline__ void cp_wait1() {
    asm volatile("cp.async.wait_group 1;" ::: "memory");
}
__device__ __forceinline__ void cp_wait0() {
    asm volatile("cp.async.wait_group 0;" ::: "memory");
}
__device__ __forceinline__ void ldsm_x4(uint32_t* r, uint32_t addr) {
    asm volatile("ldmatrix.sync.aligned.m8n8.x4.shared.b16 {%0,%1,%2,%3}, [%4];"
                 : "=r"(r[0]), "=r"(r[1]), "=r"(r[2]), "=r"(r[3]) : "r"(addr));
}
__device__ __forceinline__ void ldsm_x4_t(uint32_t* r, uint32_t addr) {
    asm volatile("ldmatrix.sync.aligned.m8n8.x4.trans.shared.b16 {%0,%1,%2,%3}, [%4];"
                 : "=r"(r[0]), "=r"(r[1]), "=r"(r[2]), "=r"(r[3]) : "r"(addr));
}
__device__ __forceinline__ void mma_bf16(float* d, const uint32_t* a, uint32_t b0, uint32_t b1) {
    asm volatile("mma.sync.aligned.m16n8k16.row.col.f32.bf16.bf16.f32 "
                 "{%0,%1,%2,%3}, {%4,%5,%6,%7}, {%8,%9}, {%0,%1,%2,%3};"
                 : "+f"(d[0]), "+f"(d[1]), "+f"(d[2]), "+f"(d[3])
                 : "r"(a[0]), "r"(a[1]), "r"(a[2]), "r"(a[3]), "r"(b0), "r"(b1));
}
__device__ __forceinline__ float gelu_exact(float v) {
    return 0.5f * v * (1.0f + erff(v * 0.70710678118654752f));
}
__device__ __forceinline__ void split_store2(__nv_bfloat16* Hi, __nv_bfloat16* Lo,
                                             size_t off, float a, float b) {
    __nv_bfloat16 ha = __float2bfloat16(a), hb = __float2bfloat16(b);
    __nv_bfloat162 hv; hv.x = ha; hv.y = hb;
    *(__nv_bfloat162*)(Hi + off) = hv;
    __nv_bfloat162 lv;
    lv.x = __float2bfloat16(a - __bfloat162float(ha));
    lv.y = __float2bfloat16(b - __bfloat162float(hb));
    *(__nv_bfloat162*)(Lo + off) = lv;
}
// pack (a,b) into bf16x2 hi + bf16x2 lo registers (low 16 bits = a)
__device__ __forceinline__ void pack_split(float a, float b, uint32_t& hi, uint32_t& lo) {
    __nv_bfloat16 ha = __float2bfloat16(a), hb = __float2bfloat16(b);
    __nv_bfloat16 la = __float2bfloat16(a - __bfloat162float(ha));
    __nv_bfloat16 lb = __float2bfloat16(b - __bfloat162float(hb));
    hi = (uint32_t)__bfloat16_as_ushort(ha) | ((uint32_t)__bfloat16_as_ushort(hb) << 16);
    lo = (uint32_t)__bfloat16_as_ushort(la) | ((uint32_t)__bfloat16_as_ushort(lb) << 16);
}

// ---------------------------------------------------------------------------
// Weight split: fp32 -> (hi, lo) bf16, vectorized x4
// ---------------------------------------------------------------------------
__global__ void split_kernel(const float4* __restrict__ src,
                             __nv_bfloat16* __restrict__ hi,
                             __nv_bfloat16* __restrict__ lo, int n4)
{
    int i = blockIdx.x * 256 + threadIdx.x;
    if (i >= n4) return;
    float4 v = src[i];
    size_t off = (size_t)i * 4;
    split_store2(hi, lo, off,     v.x, v.y);
    split_store2(hi, lo, off + 2, v.z, v.w);
}

// ---------------------------------------------------------------------------
// Pack QKV weights+biases (vectorized float4). Wq/bq pre-scaled by 1/8 so the
// attention kernel needs no Q scaling.
// ---------------------------------------------------------------------------
__global__ __launch_bounds__(256) void pack_qkv_kernel(
    const float* __restrict__ Wq, const float* __restrict__ Wk,
    const float* __restrict__ Wv,
    const float* __restrict__ bq, const float* __restrict__ bk,
    const float* __restrict__ bv,
    __nv_bfloat16* __restrict__ Whi, __nv_bfloat16* __restrict__ Wlo,
    float* __restrict__ bias)
{
    const int NV4 = NQKV / 4;                          // 576
    int i = blockIdx.x * 256 + threadIdx.x;            // < L*D*NV4
    if (i >= L_LAYERS * D_MODEL * NV4) return;
    int n4  = i % NV4;
    int rem = i / NV4;
    int k   = rem % D_MODEL;
    int l   = rem / D_MODEL;
    int n   = n4 * 4;
    int sel = n / P_PROJ;
    int col = n % P_PROJ;
    const float sc = (sel == 0) ? 0.125f : 1.0f;
    const float* W = (sel == 0) ? Wq : (sel == 1) ? Wk : Wv;
    float4 v = *(const float4*)&W[((size_t)l * D_MODEL + k) * P_PROJ + col];
    v.x *= sc; v.y *= sc; v.z *= sc; v.w *= sc;
    size_t o = ((size_t)l * D_MODEL + k) * NQKV + n;
    split_store2(Whi, Wlo, o,     v.x, v.y);
    split_store2(Whi, Wlo, o + 2, v.z, v.w);
    if (k == 0) {
        const float* bb = (sel == 0) ? bq : (sel == 1) ? bk : bv;
        float4 bv4 = *(const float4*)&bb[l * P_PROJ + col];
        bv4.x *= sc; bv4.y *= sc; bv4.z *= sc; bv4.w *= sc;
        *(float4*)&bias[(size_t)l * NQKV + n] = bv4;
    }
}

// ---------------------------------------------------------------------------
// Embedding
// ---------------------------------------------------------------------------
__global__ void embed_kernel(const int* __restrict__ idx,
                             const float* __restrict__ tok,
                             const float* __restrict__ pos,
                             float* __restrict__ x)
{
    int r = blockIdx.x;
    int t = r & (T_SEQ - 1);
    int token = idx[r];
    const float* te = tok + (size_t)token * D_MODEL;
    const float* pe = pos + (size_t)t * D_MODEL;
    float* xr = x + (size_t)r * D_MODEL;
    for (int c = threadIdx.x; c < D_MODEL; c += 256)
        xr[c] = te[c] + pe[c];
}

// ---------------------------------------------------------------------------
// LayerNorm -> split bf16 (hi, lo)   (plain variant: layer-0 ln1)
// ---------------------------------------------------------------------------
__global__ __launch_bounds__(256) void layernorm_split_kernel(
    const float* __restrict__ x, const float* __restrict__ g,
    const float* __restrict__ b,
    __nv_bfloat16* __restrict__ ohi, __nv_bfloat16* __restrict__ olo)
{
    int row = blockIdx.x;
    const float* xr = x + (size_t)row * D_MODEL;
    int t = threadIdx.x;
    float v0 = xr[t], v1 = xr[t + 256], v2 = xr[t + 512];
    float s  = v0 + v1 + v2;
    float sq = v0 * v0 + v1 * v1 + v2 * v2;
    #pragma unroll
    for (int off = 16; off > 0; off >>= 1) {
        s  += __shfl_xor_sync(0xffffffffu, s,  off);
        sq += __shfl_xor_sync(0xffffffffu, sq, off);
    }
    __shared__ float ss[8], sqq[8];
    if ((t & 31) == 0) { ss[t >> 5] = s; sqq[t >> 5] = sq; }
    __syncthreads();
    float ts = 0.f, tsq = 0.f;
    #pragma unroll
    for (int i = 0; i < 8; i++) { ts += ss[i]; tsq += sqq[i]; }
    const float inv = 1.0f / (float)D_MODEL;
    float mu  = ts * inv;
    float var = tsq * inv - mu * mu;
    float r   = rsqrtf(var + LN_EPS);

    size_t base = (size_t)row * D_MODEL;
    #pragma unroll
    for (int i = 0; i < 3; i++) {
        int c = t + i * 256;
        float v = (i == 0 ? v0 : (i == 1 ? v1 : v2));
        float o = (v - mu) * r * g[c] + b[c];
        __nv_bfloat16 h = __float2bfloat16(o);
        ohi[base + c] = h;
        olo[base + c] = __float2bfloat16(o - __bfloat162float(h));
    }
}

// ---------------------------------------------------------------------------
// Fused split-K(x3) reduce + residual + LayerNorm -> split bf16.
// ---------------------------------------------------------------------------
__global__ __launch_bounds__(256) void ln_residual_split_kernel(
    float* __restrict__ x,
    const float* __restrict__ p0, const float* __restrict__ p1,
    const float* __restrict__ p2,
    const float* __restrict__ bias,
    const float* __restrict__ g, const float* __restrict__ b,
    __nv_bfloat16* __restrict__ ohi, __nv_bfloat16* __restrict__ olo)
{
    int row = blockIdx.x;
    size_t base = (size_t)row * D_MODEL;
    int t = threadIdx.x;

    float v0, v1, v2;
    {
        int c0 = t, c1 = t + 256, c2 = t + 512;
        v0 = x[base + c0] + p0[base + c0] + p1[base + c0] + p2[base + c0] + bias[c0];
        v1 = x[base + c1] + p0[base + c1] + p1[base + c1] + p2[base + c1] + bias[c1];
        v2 = x[base + c2] + p0[base + c2] + p1[base + c2] + p2[base + c2] + bias[c2];
        x[base + c0] = v0;
        x[base + c1] = v1;
        x[base + c2] = v2;
    }

    float s  = v0 + v1 + v2;
    float sq = v0 * v0 + v1 * v1 + v2 * v2;
    #pragma unroll
    for (int off = 16; off > 0; off >>= 1) {
        s  += __shfl_xor_sync(0xffffffffu, s,  off);
        sq += __shfl_xor_sync(0xffffffffu, sq, off);
    }
    __shared__ float ss[8], sqq[8];
    if ((t & 31) == 0) { ss[t >> 5] = s; sqq[t >> 5] = sq; }
    __syncthreads();
    float ts = 0.f, tsq = 0.f;
    #pragma unroll
    for (int i = 0; i < 8; i++) { ts += ss[i]; tsq += sqq[i]; }
    const float inv = 1.0f / (float)D_MODEL;
    float mu  = ts * inv;
    float var = tsq * inv - mu * mu;
    float r   = rsqrtf(var + LN_EPS);

    #pragma unroll
    for (int i = 0; i < 3; i++) {
        int c = t + i * 256;
        float v = (i == 0 ? v0 : (i == 1 ? v1 : v2));
        float o = (v - mu) * r * g[c] + b[c];
        __nv_bfloat16 h = __float2bfloat16(o);
        ohi[base + c] = h;
        olo[base + c] = __float2bfloat16(o - __bfloat162float(h));
    }
}

// ---------------------------------------------------------------------------
// Split-bf16 tensor-core GEMM. 2-stage cp.async double buffer + software-
// pipelined fragments: B fragments double-buffered (prefetch step+1 before
// step's MMAs), A fragments reloaded for ks=1 after step 3's MMAs issue, so
// LDS traffic overlaps tensor work instead of phase-alternating with it
// (R13 model: serialized LDS(1536cyc)+MMA(2758cyc) => 64% tensor, matches
// measured 62.8%; overlapped should reach ~85%).
// EPI: 1 = +bias, exact GELU -> split bf16 (Chi, Clo)
//      3 = plain -> f32 C
//      4 = split-K partial (gridDim.z=3): z-th K-third -> C + z*M*N, f32
//      5 = +bias -> split bf16 (Chi, Clo)          [QKV output]
// ---------------------------------------------------------------------------
#define BM 128
#define BN 128
#define BK 32
#define PA 40
#define PB 136
#define AS_ELEMS (BM * PA)
#define BS_ELEMS (BK * PB)
#define STAGE_ELEMS (2 * AS_ELEMS + 2 * BS_ELEMS)
#define GEMM_SMEM_BYTES (2 * STAGE_ELEMS * 2)      // 75776

template <int EPI>
__global__ __launch_bounds__(256, 2) void hgemm_kernel(
    const __nv_bfloat16* __restrict__ Ahi, const __nv_bfloat16* __restrict__ Alo,
    const __nv_bfloat16* __restrict__ Bhi, const __nv_bfloat16* __restrict__ Blo,
    const float* __restrict__ bias,
    float* __restrict__ C,
    __nv_bfloat16* __restrict__ Chi, __nv_bfloat16* __restrict__ Clo,
    int M, int N, int K)
{
    extern __shared__ __nv_bfloat16 sm[];
    const uint32_t smem_base = smem_u32(sm);
    const uint32_t stage_bytes = STAGE_ELEMS * 2;
    const uint32_t offAhi = 0;
    const uint32_t offAlo = AS_ELEMS * 2;
    const uint32_t offBhi = 2 * AS_ELEMS * 2;
    const uint32_t offBlo = (2 * AS_ELEMS + BS_ELEMS) * 2;

    const int tid  = threadIdx.x;
    const int lane = tid & 31;
    const int wid  = tid >> 5;
    const int warp_m = wid >> 1;
    const int warp_n = wid & 1;
    const int bm = blockIdx.y * BM;
    const int bn = blockIdx.x * BN;

    const int  Keff = (EPI == 4) ? (K / 3) : K;
    const int  kz   = (EPI == 4) ? (int)blockIdx.z : 0;
    const size_t kOff = (size_t)kz * Keff;
    float* Cout = (EPI == 4) ? (C + (size_t)kz * M * N) : C;

    const int a_row = tid >> 2;
    const int a_q   = tid & 3;
    const int b_row = tid >> 4;
    const int b_q   = tid & 15;

    float acc[2][8][4];
    #pragma unroll
    for (int i = 0; i < 2; i++)
        #pragma unroll
        for (int j = 0; j < 8; j++)
            #pragma unroll
            for (int t = 0; t < 4; t++) acc[i][j][t] = 0.f;

    const int n_tiles = Keff / BK;

    auto load_stage = [&](int s, int k0) {
        uint32_t base = smem_base + s * stage_bytes;
        #pragma unroll
        for (int j = 0; j < 2; j++) {
            int ar = a_row + j * 64;
            const __nv_bfloat16* srcA = Ahi + (size_t)(bm + ar) * K + kOff + k0 + a_q * 8;
            uint32_t dstA = base + offAhi + (ar * PA + a_q * 8) * 2;
            cp_async16(dstA, srcA);
            const __nv_bfloat16* srcAl = Alo + (size_t)(bm + ar) * K + kOff + k0 + a_q * 8;
            cp_async16(dstA + (offAlo - offAhi), srcAl);

            int br = b_row + j * 16;
            const __nv_bfloat16* srcB = Bhi + (kOff + (size_t)(k0 + br)) * N + bn + b_q * 8;
            uint32_t dstB = base + offBhi + (br * PB + b_q * 8) * 2;
            cp_async16(dstB, srcB);
            const __nv_bfloat16* srcBl = Blo + (kOff + (size_t)(k0 + br)) * N + bn + b_q * 8;
            cp_async16(dstB + (offBlo - offBhi), srcBl);
        }
    };

    load_stage(0, 0);
    cp_commit();

    const int lr = lane & 15;
    const int lc = (lane >> 4) * 8;

    for (int t = 0; t < n_tiles; t++) {
        int cur = t & 1;
        if (t + 1 < n_tiles) {
            load_stage((t + 1) & 1, (t + 1) * BK);
            cp_commit();
            cp_wait1();
        } else {
            cp_wait0();
        }
        __syncthreads();

        uint32_t base = smem_base + cur * stage_bytes;

        uint32_t a_hi[2][4], a_lo[2][4];     // A frags for current ks
        uint32_t bh[2][4], bl[2][4];         // double-buffered B frags

        // prologue: A frags for ks=0, B frags for (ks=0, bi=0)
        #pragma unroll
        for (int mi = 0; mi < 2; mi++) {
            uint32_t addr = base + offAhi +
                ((warp_m * 32 + mi * 16 + lr) * PA + 0 + lc) * 2;
            ldsm_x4(a_hi[mi], addr);
            ldsm_x4(a_lo[mi], addr + (offAlo - offAhi));
        }
        {
            uint32_t addr = base + offBhi +
                ((0 + lr) * PB + warp_n * 64 + 0 * 16 + lc) * 2;
            ldsm_x4_t(bh[0], addr);
            ldsm_x4_t(bl[0], addr + (offBlo - offBhi));
        }

        // 8 steps = 2 ks x 4 bi; prefetch B for step+1 before step's MMAs
        #pragma unroll
        for (int step = 0; step < 8; step++) {
            const int bi  = step & 3;
            const int cb  = step & 1;
            if (step < 7) {
                const int ns  = step + 1;
                const int nks = (ns >> 2) * 16;
                const int nbi = ns & 3;
                uint32_t addr = base + offBhi +
                    ((nks + lr) * PB + warp_n * 64 + nbi * 16 + lc) * 2;
                ldsm_x4_t(bh[cb ^ 1], addr);
                ldsm_x4_t(bl[cb ^ 1], addr + (offBlo - offBhi));
            }
            #pragma unroll
            for (int mi = 0; mi < 2; mi++) {
                const int ni0 = bi * 2, ni1 = bi * 2 + 1;
                mma_bf16(acc[mi][ni0], a_hi[mi], bh[cb][0], bh[cb][1]);
                mma_bf16(acc[mi][ni0], a_hi[mi], bl[cb][0], bl[cb][1]);
                mma_bf16(acc[mi][ni0], a_lo[mi], bh[cb][0], bh[cb][1]);
                mma_bf16(acc[mi][ni1], a_hi[mi], bh[cb][2], bh[cb][3]);
                mma_bf16(acc[mi][ni1], a_hi[mi], bl[cb][2], bl[cb][3]);
                mma_bf16(acc[mi][ni1], a_lo[mi], bh[cb][2], bh[cb][3]);
            }
            if (step == 3) {
                // reload A frags for ks=1 (after their last consumers issued)
                #pragma unroll
                for (int mi = 0; mi < 2; mi++) {
                    uint32_t addr = base + offAhi +
                        ((warp_m * 32 + mi * 16 + lr) * PA + 16 + lc) * 2;
                    ldsm_x4(a_hi[mi], addr);
                    ldsm_x4(a_lo[mi], addr + (offAlo - offAhi));
                }
            }
        }
        __syncthreads();
    }

    const int g = lane >> 2, tig = lane & 3;
    #pragma unroll
    for (int mi = 0; mi < 2; mi++) {
        #pragma unroll
        for (int ni = 0; ni < 8; ni++) {
            int r0 = bm + warp_m * 32 + mi * 16 + g;
            int r1 = r0 + 8;
            int c  = bn + warp_n * 64 + ni * 8 + tig * 2;
            float v00 = acc[mi][ni][0], v01 = acc[mi][ni][1];
            float v10 = acc[mi][ni][2], v11 = acc[mi][ni][3];
            if (EPI != 3 && EPI != 4) {
                float b0 = bias[c], b1 = bias[c + 1];
                v00 += b0; v01 += b1; v10 += b0; v11 += b1;
            }
            if (EPI == 1 || EPI == 5) {
                if (EPI == 1) {
                    v00 = gelu_exact(v00); v01 = gelu_exact(v01);
                    v10 = gelu_exact(v10); v11 = gelu_exact(v11);
                }
                split_store2(Chi, Clo, (size_t)r0 * N + c, v00, v01);
                split_store2(Chi, Clo, (size_t)r1 * N + c, v10, v11);
            } else {
                float2 o0 = make_float2(v00, v01);
                float2 o1 = make_float2(v10, v11);
                *(float2*)&Cout[(size_t)r0 * N + c] = o0;
                *(float2*)&Cout[(size_t)r1 * N + c] = o1;
            }
        }
    }
}

// ---------------------------------------------------------------------------
// Tensor-core flash attention, split-bf16 inputs via cp.async.
// One CTA (4 warps) per (b, h, 64-query tile); key tiles of 64.
// ---------------------------------------------------------------------------
#define ATT_TILE_B 8192                              // 64 x 128 B
#define ATT_SMEM_BYTES (6 * ATT_TILE_B + 256)        // 49408

__global__ __launch_bounds__(128) void attn_tc_kernel(
    const __nv_bfloat16* __restrict__ Qh_g, const __nv_bfloat16* __restrict__ Ql_g,
    const float* __restrict__ mask,
    __nv_bfloat16* __restrict__ Yhi, __nv_bfloat16* __restrict__ Ylo)
{
    extern __shared__ __nv_bfloat16 smb[];
    const uint32_t sb = smem_u32(smb);
    float* maskS = (float*)(smb + 6 * (ATT_TILE_B / 2));

    const uint32_t oK = 2 * ATT_TILE_B;   // Khi
    const uint32_t oV = 4 * ATT_TILE_B;   // Vhi
    const uint32_t dHL = ATT_TILE_B;      // hi -> lo byte offset

    const int b  = blockIdx.y / N_HEADS;
    const int h  = blockIdx.y % N_HEADS;
    const int qb = blockIdx.x * 64;
    const int tid = threadIdx.x, lane = tid & 31, w = tid >> 5;
    const size_t bT = (size_t)b * T_SEQ;

    // Q tile: 512 16B-chunks per buffer, 4 per thread (joins first commit group)
    #pragma unroll
    for (int i = 0; i < 4; i++) {
        int idx = tid + i * 128;
        int r = idx >> 3, cc = idx & 7;
        uint32_t dsw = (uint32_t)(r * 128 + ((cc << 4) ^ ((r & 7) << 4)));
        size_t src = (bT + qb + r) * NQKV + h * HD + cc * 8;
        cp_async16(sb + dsw,       Qh_g + src);
        cp_async16(sb + dHL + dsw, Ql_g + src);
    }

    float yacc[8][4];
    #pragma unroll
    for (int j = 0; j < 8; j++)
        #pragma unroll
        for (int t = 0; t < 4; t++) yacc[j][t] = 0.f;

    float m0 = -1e30f, m8 = -1e30f, l0 = 0.f, l8 = 0.f;
    const int g  = lane >> 2;
    const int c2 = (lane & 3) * 2;
    const int qrow0 = qb + w * 16 + g;
    const int qrow8 = qrow0 + 8;
    const int lr = lane & 15;
    const int hc = (lane >> 4);            // 0/1: high 16B chunk select

    for (int kb = 0; kb <= qb; kb += 64) {
        __syncthreads();   // previous tile's consumers done
        #pragma unroll
        for (int i = 0; i < 4; i++) {
            int idx = tid + i * 128;
            int r = idx >> 3, cc = idx & 7;
            uint32_t dsw = (uint32_t)(r * 128 + ((cc << 4) ^ ((r & 7) << 4)));
            size_t src = (bT + kb + r) * NQKV + h * HD + cc * 8;
            cp_async16(sb + oK + dsw,       Qh_g + P_PROJ + src);
            cp_async16(sb + oK + dHL + dsw, Ql_g + P_PROJ + src);
            cp_async16(sb + oV + dsw,       Qh_g + 2 * P_PROJ + src);
            cp_async16(sb + oV + dHL + dsw, Ql_g + 2 * P_PROJ + src);
        }
        cp_commit();
        if (tid < 64) maskS[tid] = mask[b * T_SEQ + kb + tid];
        cp_wait0();
        __syncthreads();

        // ---- S = Q K^T ----
        float sacc[8][4];
        #pragma unroll
        for (int j = 0; j < 8; j++)
            #pragma unroll
            for (int t = 0; t < 4; t++) sacc[j][t] = 0.f;

        #pragma unroll
        for (int ks = 0; ks < 4; ks++) {
            uint32_t ahi[4], alo[4];
            int ar = w * 16 + lr;
            int accc = ks * 2 + hc;
            uint32_t aaddr = sb + (uint32_t)(ar * 128 + ((accc << 4) ^ ((ar & 7) << 4)));
            ldsm_x4(ahi, aaddr);
            ldsm_x4(alo, aaddr + dHL);
            #pragma unroll
            for (int nb = 0; nb < 4; nb++) {
                uint32_t kh[4], kl[4];
                int kr = nb * 16 + lr;
                uint32_t kaddr = sb + oK + (uint32_t)(kr * 128 + ((accc << 4) ^ ((kr & 7) << 4)));
                ldsm_x4(kh, kaddr);
                ldsm_x4(kl, kaddr + dHL);
                int j0 = nb * 2, j1 = nb * 2 + 1;
                mma_bf16(sacc[j0], ahi, kh[0], kh[2]);
                mma_bf16(sacc[j0], ahi, kl[0], kl[2]);
                mma_bf16(sacc[j0], alo, kh[0], kh[2]);
                mma_bf16(sacc[j1], ahi, kh[1], kh[3]);
                mma_bf16(sacc[j1], ahi, kl[1], kl[3]);
                mma_bf16(sacc[j1], alo, kh[1], kh[3]);
            }
        }

        // ---- mask + online softmax ----
        float mx0 = -1e30f, mx8 = -1e30f;
        #pragma unroll
        for (int j = 0; j < 8; j++) {
            int k0 = kb + j * 8 + c2;
            float ms0 = maskS[j * 8 + c2], ms1 = maskS[j * 8 + c2 + 1];
            if (k0     > qrow0 || ms0 == 0.f) sacc[j][0] = -1e30f;
            if (k0 + 1 > qrow0 || ms1 == 0.f) sacc[j][1] = -1e30f;
            if (k0     > qrow8 || ms0 == 0.f) sacc[j][2] = -1e30f;
            if (k0 + 1 > qrow8 || ms1 == 0.f) sacc[j][3] = -1e30f;
            mx0 = fmaxf(mx0, fmaxf(sacc[j][0], sacc[j][1]));
            mx8 = fmaxf(mx8, fmaxf(sacc[j][2], sacc[j][3]));
        }
        mx0 = fmaxf(mx0, __shfl_xor_sync(0xffffffffu, mx0, 1));
        mx0 = fmaxf(mx0, __shfl_xor_sync(0xffffffffu, mx0, 2));
        mx8 = fmaxf(mx8, __shfl_xor_sync(0xffffffffu, mx8, 1));
        mx8 = fmaxf(mx8, __shfl_xor_sync(0xffffffffu, mx8, 2));

        float nm0 = fmaxf(m0, mx0), nm8 = fmaxf(m8, mx8);
        float corr0 = __expf(m0 - nm0), corr8 = __expf(m8 - nm8);
        m0 = nm0; m8 = nm8;

        float ps0 = 0.f, ps8 = 0.f;
        #pragma unroll
        for (int j = 0; j < 8; j++) {
            sacc[j][0] = __expf(sacc[j][0] - nm0);
            sacc[j][1] = __expf(sacc[j][1] - nm0);
            sacc[j][2] = __expf(sacc[j][2] - nm8);
            sacc[j][3] = __expf(sacc[j][3] - nm8);
            ps0 += sacc[j][0] + sacc[j][1];
            ps8 += sacc[j][2] + sacc[j][3];
        }
        ps0 += __shfl_xor_sync(0xffffffffu, ps0, 1);
        ps0 += __shfl_xor_sync(0xffffffffu, ps0, 2);
        ps8 += __shfl_xor_sync(0xffffffffu, ps8, 1);
        ps8 += __shfl_xor_sync(0xffffffffu, ps8, 2);
        l0 = l0 * corr0 + ps0;
        l8 = l8 * corr8 + ps8;

        #pragma unroll
        for (int j = 0; j < 8; j++) {
            yacc[j][0] *= corr0; yacc[j][1] *= corr0;
            yacc[j][2] *= corr8; yacc[j][3] *= corr8;
        }

        // ---- Y += P V ----
        #pragma unroll
        for (int kk = 0; kk < 4; kk++) {
            uint32_t phi[4], plo[4];
            pack_split(sacc[kk * 2][0],     sacc[kk * 2][1],     phi[0], plo[0]);
            pack_split(sacc[kk * 2][2],     sacc[kk * 2][3],     phi[1], plo[1]);
            pack_split(sacc[kk * 2 + 1][0], sacc[kk * 2 + 1][1], phi[2], plo[2]);
            pack_split(sacc[kk * 2 + 1][2], sacc[kk * 2 + 1][3], phi[3], plo[3]);
            #pragma unroll
            for (int nb = 0; nb < 4; nb++) {
                uint32_t vh[4], vl[4];
                int vr = kk * 16 + lr;
                int vcc = nb * 2 + hc;
                uint32_t vaddr = sb + oV + (uint32_t)(vr * 128 + ((vcc << 4) ^ ((vr & 7) << 4)));
                ldsm_x4_t(vh, vaddr);
                ldsm_x4_t(vl, vaddr + dHL);
                int j0 = nb * 2, j1 = nb * 2 + 1;
                mma_bf16(yacc[j0], phi, vh[0], vh[1]);
                mma_bf16(yacc[j0], phi, vl[0], vl[1]);
                mma_bf16(yacc[j0], plo, vh[0], vh[1]);
                mma_bf16(yacc[j1], phi, vh[2], vh[3]);
                mma_bf16(yacc[j1], phi, vl[2], vl[3]);
                mma_bf16(yacc[j1], plo, vh[2], vh[3]);
            }
        }
    }

    // ---- normalize + split-bf16 output ----
    float inv0 = 1.0f / l0, inv8 = 1.0f / l8;
    size_t row0 = (bT + qb + w * 16 + g) * P_PROJ + h * HD;
    size_t row8 = row0 + (size_t)8 * P_PROJ;
    #pragma unroll
    for (int j = 0; j < 8; j++) {
        int col = j * 8 + c2;
        split_store2(Yhi, Ylo, row0 + col, yacc[j][0] * inv0, yacc[j][1] * inv0);
        split_store2(Yhi, Ylo, row8 + col, yacc[j][2] * inv8, yacc[j][3] * inv8);
    }
}

// ---------------------------------------------------------------------------
// Host orchestration
// ---------------------------------------------------------------------------
static void split_launch(const float* src, __nv_bfloat16* hi, __nv_bfloat16* lo, int n) {
    int n4 = n / 4;
    split_kernel<<<(n4 + 255) / 256, 256>>>((const float4*)src, hi, lo, n4);
}

extern "C" void kernel_launch(void* const* d_in, const int* in_sizes, int n_in,
                              void* d_out, int out_size)
{
    const int*   idx       = (const int*)  d_in[0];
    const float* attn_mask = (const float*)d_in[1];
    const float* tok_emb   = (const float*)d_in[2];
    const float* pos_emb   = (const float*)d_in[3];
    const float* ln1_g     = (const float*)d_in[4];
    const float* ln1_b     = (const float*)d_in[5];
    const float* Wq        = (const float*)d_in[6];
    const float* bq        = (const float*)d_in[7];
    const float* Wk        = (const float*)d_in[8];
    const float* bk        = (const float*)d_in[9];
    const float* Wv        = (const float*)d_in[10];
    const float* bv        = (const float*)d_in[11];
    const float* Wo        = (const float*)d_in[12];
    const float* bo        = (const float*)d_in[13];
    const float* ln2_g     = (const float*)d_in[14];
    const float* ln2_b     = (const float*)d_in[15];
    const float* W1        = (const float*)d_in[16];
    const float* b1        = (const float*)d_in[17];
    const float* W2        = (const float*)d_in[18];
    const float* b2        = (const float*)d_in[19];
    const float* lnf_g     = (const float*)d_in[20];
    const float* lnf_b     = (const float*)d_in[21];
    const float* W_out     = (const float*)d_in[22];
    float* out = (float*)d_out;

    float *x, *bqkv, *part;
    __nv_bfloat16 *qkv_hi, *qkv_lo;
    __nv_bfloat16 *h_hi, *h_lo, *y_hi, *y_lo, *m1_hi, *m1_lo;
    __nv_bfloat16 *wqkv_hi, *wqkv_lo;
    __nv_bfloat16 *wo_hi, *wo_lo, *w1_hi, *w1_lo, *w2_hi, *w2_lo, *wout_hi, *wout_lo;

    cudaGetSymbolAddress((void**)&x,    g_x);
    cudaGetSymbolAddress((void**)&bqkv, g_bqkv);
    cudaGetSymbolAddress((void**)&part, g_part);
    cudaGetSymbolAddress((void**)&qkv_hi, g_qkv_hi);
    cudaGetSymbolAddress((void**)&qkv_lo, g_qkv_lo);
    cudaGetSymbolAddress((void**)&h_hi,  g_h_hi);
    cudaGetSymbolAddress((void**)&h_lo,  g_h_lo);
    cudaGetSymbolAddress((void**)&y_hi,  g_y_hi);
    cudaGetSymbolAddress((void**)&y_lo,  g_y_lo);
    cudaGetSymbolAddress((void**)&m1_hi, g_m1_hi);
    cudaGetSymbolAddress((void**)&m1_lo, g_m1_lo);
    cudaGetSymbolAddress((void**)&wqkv_hi, g_wqkv_hi);
    cudaGetSymbolAddress((void**)&wqkv_lo, g_wqkv_lo);
    cudaGetSymbolAddress((void**)&wo_hi, g_wo_hi);
    cudaGetSymbolAddress((void**)&wo_lo, g_wo_lo);
    cudaGetSymbolAddress((void**)&w1_hi, g_w1_hi);
    cudaGetSymbolAddress((void**)&w1_lo, g_w1_lo);
    cudaGetSymbolAddress((void**)&w2_hi, g_w2_hi);
    cudaGetSymbolAddress((void**)&w2_lo, g_w2_lo);
    cudaGetSymbolAddress((void**)&wout_hi, g_wout_hi);
    cudaGetSymbolAddress((void**)&wout_lo, g_wout_lo);

    cudaFuncSetAttribute(hgemm_kernel<1>, cudaFuncAttributeMaxDynamicSharedMemorySize, GEMM_SMEM_BYTES);
    cudaFuncSetAttribute(hgemm_kernel<3>, cudaFuncAttributeMaxDynamicSharedMemorySize, GEMM_SMEM_BYTES);
    cudaFuncSetAttribute(hgemm_kernel<4>, cudaFuncAttributeMaxDynamicSharedMemorySize, GEMM_SMEM_BYTES);
    cudaFuncSetAttribute(hgemm_kernel<5>, cudaFuncAttributeMaxDynamicSharedMemorySize, GEMM_SMEM_BYTES);
    cudaFuncSetAttribute(attn_tc_kernel,  cudaFuncAttributeMaxDynamicSharedMemorySize, ATT_SMEM_BYTES);

    const dim3 gqkv (NQKV / BN, ROWS / BM);          // (18, 64)
    const dim3 gsk  (P_PROJ / BN, ROWS / BM, 3);     // split-K x3 -> 1152 CTAs
    const dim3 gff  (FF_DIM / BN, ROWS / BM);        // (24, 64)
    const dim3 ghead(V_VOCAB / BN, ROWS / BM);       // (4, 64)
    const dim3 gattn(T_SEQ / 64, B_BATCH * N_HEADS); // (16, 96)
    const int  npack = (L_LAYERS * D_MODEL * (NQKV / 4) + 255) / 256;

    float* part0 = part;
    float* part1 = part + (size_t)ROWS * D_MODEL;
    float* part2 = part + (size_t)2 * ROWS * D_MODEL;

    // Launch order keeps ncu's sampled launch (index 3) = fused-QKV hgemm.
    embed_kernel<<<ROWS, 256>>>(idx, tok_emb, pos_emb, x);                               // 0
    layernorm_split_kernel<<<ROWS, 256>>>(x, ln1_g, ln1_b, h_hi, h_lo);                  // 1
    pack_qkv_kernel<<<npack, 256>>>(Wq, Wk, Wv, bq, bk, bv, wqkv_hi, wqkv_lo, bqkv);     // 2
    hgemm_kernel<5><<<gqkv, 256, GEMM_SMEM_BYTES>>>(                                     // 3 <- profiled
        h_hi, h_lo, wqkv_hi, wqkv_lo, bqkv,
        nullptr, qkv_hi, qkv_lo, ROWS, NQKV, D_MODEL);
    split_launch(Wo, wo_hi, wo_lo, L_LAYERS * P_PROJ * D_MODEL);                         // 4
    split_launch(W1, w1_hi, w1_lo, L_LAYERS * D_MODEL * FF_DIM);                         // 5
    split_launch(W2, w2_hi, w2_lo, L_LAYERS * FF_DIM * D_MODEL);                         // 6
    split_launch(W_out, wout_hi, wout_lo, D_MODEL * V_VOCAB);                            // 7

    for (int l = 0; l < L_LAYERS; l++) {
        const size_t wqkvo = (size_t)l * D_MODEL * NQKV;
        const size_t wdp   = (size_t)l * D_MODEL * P_PROJ;
        const size_t wdf   = (size_t)l * D_MODEL * FF_DIM;

        attn_tc_kernel<<<gattn, 128, ATT_SMEM_BYTES>>>(qkv_hi, qkv_lo, attn_mask, y_hi, y_lo);

        // part = y @ Wo (split-K x3); fused: x += part* + bo, h = LN2(x)
        hgemm_kernel<4><<<gsk, 256, GEMM_SMEM_BYTES>>>(
            y_hi, y_lo, wo_hi + wdp, wo_lo + wdp, nullptr,
            part, nullptr, nullptr, ROWS, D_MODEL, P_PROJ);
        ln_residual_split_kernel<<<ROWS, 256>>>(
            x, part0, part1, part2, bo + l * D_MODEL,
            ln2_g + l * D_MODEL, ln2_b + l * D_MODEL, h_hi, h_lo);

        // m1 = gelu(h @ W1 + b1) -> split bf16
        hgemm_kernel<1><<<gff, 256, GEMM_SMEM_BYTES>>>(
            h_hi, h_lo, w1_hi + wdf, w1_lo + wdf, b1 + l * FF_DIM,
            nullptr, m1_hi, m1_lo, ROWS, FF_DIM, D_MODEL);
        // part = m1 @ W2 (split-K x3); fused residual + next LN
        hgemm_kernel<4><<<gsk, 256, GEMM_SMEM_BYTES>>>(
            m1_hi, m1_lo, w2_hi + wdf, w2_lo + wdf, nullptr,
            part, nullptr, nullptr, ROWS, D_MODEL, FF_DIM);

        if (l + 1 < L_LAYERS) {
            ln_residual_split_kernel<<<ROWS, 256>>>(
                x, part0, part1, part2, b2 + l * D_MODEL,
                ln1_g + (l + 1) * D_MODEL, ln1_b + (l + 1) * D_MODEL, h_hi, h_lo);
            hgemm_kernel<5><<<gqkv, 256, GEMM_SMEM_BYTES>>>(
                h_hi, h_lo, wqkv_hi + wqkvo + (size_t)D_MODEL * NQKV,
                wqkv_lo + wqkvo + (size_t)D_MODEL * NQKV, bqkv + (l + 1) * NQKV,
                nullptr, qkv_hi, qkv_lo, ROWS, NQKV, D_MODEL);
        } else {
            ln_residual_split_kernel<<<ROWS, 256>>>(
                x, part0, part1, part2, b2 + l * D_MODEL,
                lnf_g, lnf_b, h_hi, h_lo);
        }
    }

    hgemm_kernel<3><<<ghead, 256, GEMM_SMEM_BYTES>>>(
        h_hi, h_lo, wout_hi, wout_lo, nullptr,
        out, nullptr, nullptr, ROWS, V_VOCAB, D_MODEL);
}

// round 15
// speedup vs baseline: 1.0177x; 1.0177x over previous
#include <cuda_runtime.h>
#include <cuda_bf16.h>
#include <math.h>
#include <stdint.h>

// ---------------------------------------------------------------------------
// Problem constants
// ---------------------------------------------------------------------------
#define L_LAYERS 6
#define V_VOCAB  512
#define D_MODEL  768
#define P_PROJ   768
#define N_HEADS  12
#define HD       64
#define FF_DIM   3072
#define B_BATCH  8
#define T_SEQ    1024
#define ROWS     (B_BATCH * T_SEQ)   // 8192
#define LN_EPS   1e-5f
#define NQKV     (3 * P_PROJ)        // 2304

// ---------------------------------------------------------------------------
// Scratch (device globals: allocation-free rule)
// ---------------------------------------------------------------------------
__device__ float g_x   [ROWS * D_MODEL];          // residual stream (fp32)
__device__ float g_part[3 * ROWS * D_MODEL];      // split-K partials (x3)

__device__ __nv_bfloat16 g_qkv_hi[ROWS * NQKV];   // fused q|k|v split bf16
__device__ __nv_bfloat16 g_qkv_lo[ROWS * NQKV];

__device__ __nv_bfloat16 g_h_hi [ROWS * D_MODEL];
__device__ __nv_bfloat16 g_h_lo [ROWS * D_MODEL];
__device__ __nv_bfloat16 g_y_hi [ROWS * P_PROJ];
__device__ __nv_bfloat16 g_y_lo [ROWS * P_PROJ];
__device__ __nv_bfloat16 g_m1_hi[ROWS * FF_DIM];
__device__ __nv_bfloat16 g_m1_lo[ROWS * FF_DIM];

// split weights ([K,N] row-major, as hgemm consumes them)
__device__ __nv_bfloat16 g_wqkv_hi[L_LAYERS * D_MODEL * NQKV];
__device__ __nv_bfloat16 g_wqkv_lo[L_LAYERS * D_MODEL * NQKV];
__device__ float         g_bqkv  [L_LAYERS * NQKV];
__device__ __nv_bfloat16 g_wo_hi[L_LAYERS * P_PROJ * D_MODEL];
__device__ __nv_bfloat16 g_wo_lo[L_LAYERS * P_PROJ * D_MODEL];
__device__ __nv_bfloat16 g_w1_hi[L_LAYERS * D_MODEL * FF_DIM];
__device__ __nv_bfloat16 g_w1_lo[L_LAYERS * D_MODEL * FF_DIM];
__device__ __nv_bfloat16 g_w2_hi[L_LAYERS * FF_DIM * D_MODEL];
__device__ __nv_bfloat16 g_w2_lo[L_LAYERS * FF_DIM * D_MODEL];
__device__ __nv_bfloat16 g_wout_hi[D_MODEL * V_VOCAB];
__device__ __nv_bfloat16 g_wout_lo[D_MODEL * V_VOCAB];

// ---------------------------------------------------------------------------
// Small helpers
// ---------------------------------------------------------------------------
__device__ __forceinline__ uint32_t smem_u32(const void* p) {
    return (uint32_t)__cvta_generic_to_shared(p);
}
__device__ __forceinline__ void cp_async16(uint32_t dst, const void* src) {
    asm volatile("cp.async.cg.shared.global [%0], [%1], 16;" :: "r"(dst), "l"(src));
}
__device__ __forceinline__ void cp_commit() {
    asm volatile("cp.async.commit_group;");
}
__device__ __forceinline__ void cp_wait1() {
    asm volatile("cp.async.wait_group 1;" ::: "memory");
}
__device__ __forceinline__ void cp_wait0() {
    asm volatile("cp.async.wait_group 0;" ::: "memory");
}
__device__ __forceinline__ void ldsm_x4(uint32_t* r, uint32_t addr) {
    asm volatile("ldmatrix.sync.aligned.m8n8.x4.shared.b16 {%0,%1,%2,%3}, [%4];"
                 : "=r"(r[0]), "=r"(r[1]), "=r"(r[2]), "=r"(r[3]) : "r"(addr));
}
__device__ __forceinline__ void ldsm_x4_t(uint32_t* r, uint32_t addr) {
    asm volatile("ldmatrix.sync.aligned.m8n8.x4.trans.shared.b16 {%0,%1,%2,%3}, [%4];"
                 : "=r"(r[0]), "=r"(r[1]), "=r"(r[2]), "=r"(r[3]) : "r"(addr));
}
__device__ __forceinline__ void mma_bf16(float* d, const uint32_t* a, uint32_t b0, uint32_t b1) {
    asm volatile("mma.sync.aligned.m16n8k16.row.col.f32.bf16.bf16.f32 "
                 "{%0,%1,%2,%3}, {%4,%5,%6,%7}, {%8,%9}, {%0,%1,%2,%3};"
                 : "+f"(d[0]), "+f"(d[1]), "+f"(d[2]), "+f"(d[3])
                 : "r"(a[0]), "r"(a[1]), "r"(a[2]), "r"(a[3]), "r"(b0), "r"(b1));
}
__device__ __forceinline__ float gelu_exact(float v) {
    return 0.5f * v * (1.0f + erff(v * 0.70710678118654752f));
}
__device__ __forceinline__ void split_store2(__nv_bfloat16* Hi, __nv_bfloat16* Lo,
                                             size_t off, float a, float b) {
    __nv_bfloat16 ha = __float2bfloat16(a), hb = __float2bfloat16(b);
    __nv_bfloat162 hv; hv.x = ha; hv.y = hb;
    *(__nv_bfloat162*)(Hi + off) = hv;
    __nv_bfloat162 lv;
    lv.x = __float2bfloat16(a - __bfloat162float(ha));
    lv.y = __float2bfloat16(b - __bfloat162float(hb));
    *(__nv_bfloat162*)(Lo + off) = lv;
}
// pack (a,b) into bf16x2 hi + bf16x2 lo registers (low 16 bits = a)
__device__ __forceinline__ void pack_split(float a, float b, uint32_t& hi, uint32_t& lo) {
    __nv_bfloat16 ha = __float2bfloat16(a), hb = __float2bfloat16(b);
    __nv_bfloat16 la = __float2bfloat16(a - __bfloat162float(ha));
    __nv_bfloat16 lb = __float2bfloat16(b - __bfloat162float(hb));
    hi = (uint32_t)__bfloat16_as_ushort(ha) | ((uint32_t)__bfloat16_as_ushort(hb) << 16);
    lo = (uint32_t)__bfloat16_as_ushort(la) | ((uint32_t)__bfloat16_as_ushort(lb) << 16);
}

// ---------------------------------------------------------------------------
// Weight split: fp32 -> (hi, lo) bf16, vectorized x4
// ---------------------------------------------------------------------------
__global__ void split_kernel(const float4* __restrict__ src,
                             __nv_bfloat16* __restrict__ hi,
                             __nv_bfloat16* __restrict__ lo, int n4)
{
    int i = blockIdx.x * 256 + threadIdx.x;
    if (i >= n4) return;
    float4 v = src[i];
    size_t off = (size_t)i * 4;
    split_store2(hi, lo, off,     v.x, v.y);
    split_store2(hi, lo, off + 2, v.z, v.w);
}

// ---------------------------------------------------------------------------
// Pack QKV weights+biases (vectorized float4). Wq/bq pre-scaled by 1/8 so the
// attention kernel needs no Q scaling.
// ---------------------------------------------------------------------------
__global__ __launch_bounds__(256) void pack_qkv_kernel(
    const float* __restrict__ Wq, const float* __restrict__ Wk,
    const float* __restrict__ Wv,
    const float* __restrict__ bq, const float* __restrict__ bk,
    const float* __restrict__ bv,
    __nv_bfloat16* __restrict__ Whi, __nv_bfloat16* __restrict__ Wlo,
    float* __restrict__ bias)
{
    const int NV4 = NQKV / 4;                          // 576
    int i = blockIdx.x * 256 + threadIdx.x;            // < L*D*NV4
    if (i >= L_LAYERS * D_MODEL * NV4) return;
    int n4  = i % NV4;
    int rem = i / NV4;
    int k   = rem % D_MODEL;
    int l   = rem / D_MODEL;
    int n   = n4 * 4;
    int sel = n / P_PROJ;
    int col = n % P_PROJ;
    const float sc = (sel == 0) ? 0.125f : 1.0f;
    const float* W = (sel == 0) ? Wq : (sel == 1) ? Wk : Wv;
    float4 v = *(const float4*)&W[((size_t)l * D_MODEL + k) * P_PROJ + col];
    v.x *= sc; v.y *= sc; v.z *= sc; v.w *= sc;
    size_t o = ((size_t)l * D_MODEL + k) * NQKV + n;
    split_store2(Whi, Wlo, o,     v.x, v.y);
    split_store2(Whi, Wlo, o + 2, v.z, v.w);
    if (k == 0) {
        const float* bb = (sel == 0) ? bq : (sel == 1) ? bk : bv;
        float4 bv4 = *(const float4*)&bb[l * P_PROJ + col];
        bv4.x *= sc; bv4.y *= sc; bv4.z *= sc; bv4.w *= sc;
        *(float4*)&bias[(size_t)l * NQKV + n] = bv4;
    }
}

// ---------------------------------------------------------------------------
// Embedding
// ---------------------------------------------------------------------------
__global__ void embed_kernel(const int* __restrict__ idx,
                             const float* __restrict__ tok,
                             const float* __restrict__ pos,
                             float* __restrict__ x)
{
    int r = blockIdx.x;
    int t = r & (T_SEQ - 1);
    int token = idx[r];
    const float* te = tok + (size_t)token * D_MODEL;
    const float* pe = pos + (size_t)t * D_MODEL;
    float* xr = x + (size_t)r * D_MODEL;
    for (int c = threadIdx.x; c < D_MODEL; c += 256)
        xr[c] = te[c] + pe[c];
}

// ---------------------------------------------------------------------------
// LayerNorm -> split bf16 (hi, lo)   (plain variant: layer-0 ln1)
// ---------------------------------------------------------------------------
__global__ __launch_bounds__(256) void layernorm_split_kernel(
    const float* __restrict__ x, const float* __restrict__ g,
    const float* __restrict__ b,
    __nv_bfloat16* __restrict__ ohi, __nv_bfloat16* __restrict__ olo)
{
    int row = blockIdx.x;
    const float* xr = x + (size_t)row * D_MODEL;
    int t = threadIdx.x;
    float v0 = xr[t], v1 = xr[t + 256], v2 = xr[t + 512];
    float s  = v0 + v1 + v2;
    float sq = v0 * v0 + v1 * v1 + v2 * v2;
    #pragma unroll
    for (int off = 16; off > 0; off >>= 1) {
        s  += __shfl_xor_sync(0xffffffffu, s,  off);
        sq += __shfl_xor_sync(0xffffffffu, sq, off);
    }
    __shared__ float ss[8], sqq[8];
    if ((t & 31) == 0) { ss[t >> 5] = s; sqq[t >> 5] = sq; }
    __syncthreads();
    float ts = 0.f, tsq = 0.f;
    #pragma unroll
    for (int i = 0; i < 8; i++) { ts += ss[i]; tsq += sqq[i]; }
    const float inv = 1.0f / (float)D_MODEL;
    float mu  = ts * inv;
    float var = tsq * inv - mu * mu;
    float r   = rsqrtf(var + LN_EPS);

    size_t base = (size_t)row * D_MODEL;
    #pragma unroll
    for (int i = 0; i < 3; i++) {
        int c = t + i * 256;
        float v = (i == 0 ? v0 : (i == 1 ? v1 : v2));
        float o = (v - mu) * r * g[c] + b[c];
        __nv_bfloat16 h = __float2bfloat16(o);
        ohi[base + c] = h;
        olo[base + c] = __float2bfloat16(o - __bfloat162float(h));
    }
}

// ---------------------------------------------------------------------------
// Fused split-K(x3) reduce + residual + LayerNorm -> split bf16.
// ---------------------------------------------------------------------------
__global__ __launch_bounds__(256) void ln_residual_split_kernel(
    float* __restrict__ x,
    const float* __restrict__ p0, const float* __restrict__ p1,
    const float* __restrict__ p2,
    const float* __restrict__ bias,
    const float* __restrict__ g, const float* __restrict__ b,
    __nv_bfloat16* __restrict__ ohi, __nv_bfloat16* __restrict__ olo)
{
    int row = blockIdx.x;
    size_t base = (size_t)row * D_MODEL;
    int t = threadIdx.x;

    float v0, v1, v2;
    {
        int c0 = t, c1 = t + 256, c2 = t + 512;
        v0 = x[base + c0] + p0[base + c0] + p1[base + c0] + p2[base + c0] + bias[c0];
        v1 = x[base + c1] + p0[base + c1] + p1[base + c1] + p2[base + c1] + bias[c1];
        v2 = x[base + c2] + p0[base + c2] + p1[base + c2] + p2[base + c2] + bias[c2];
        x[base + c0] = v0;
        x[base + c1] = v1;
        x[base + c2] = v2;
    }

    float s  = v0 + v1 + v2;
    float sq = v0 * v0 + v1 * v1 + v2 * v2;
    #pragma unroll
    for (int off = 16; off > 0; off >>= 1) {
        s  += __shfl_xor_sync(0xffffffffu, s,  off);
        sq += __shfl_xor_sync(0xffffffffu, sq, off);
    }
    __shared__ float ss[8], sqq[8];
    if ((t & 31) == 0) { ss[t >> 5] = s; sqq[t >> 5] = sq; }
    __syncthreads();
    float ts = 0.f, tsq = 0.f;
    #pragma unroll
    for (int i = 0; i < 8; i++) { ts += ss[i]; tsq += sqq[i]; }
    const float inv = 1.0f / (float)D_MODEL;
    float mu  = ts * inv;
    float var = tsq * inv - mu * mu;
    float r   = rsqrtf(var + LN_EPS);

    #pragma unroll
    for (int i = 0; i < 3; i++) {
        int c = t + i * 256;
        float v = (i == 0 ? v0 : (i == 1 ? v1 : v2));
        float o = (v - mu) * r * g[c] + b[c];
        __nv_bfloat16 h = __float2bfloat16(o);
        ohi[base + c] = h;
        olo[base + c] = __float2bfloat16(o - __bfloat162float(h));
    }
}

// ---------------------------------------------------------------------------
// Split-bf16 tensor-core GEMM (R13 structure: 2-stage cp.async double buffer).
// R15 change: per bi-block the 12 MMAs are issued TERM-MAJOR across the four
// independent accumulators (mi x ni-half) so no two consecutive MMAs share an
// accumulator (was: 3 back-to-back same-acc MMAs -> RAW stalls, tensor ~62%).
// Per-accumulator order stays hh -> hl -> lh: bit-identical results.
// EPI: 1 = +bias, exact GELU -> split bf16 (Chi, Clo)
//      3 = plain -> f32 C
//      4 = split-K partial (gridDim.z=3): z-th K-third -> C + z*M*N, f32
//      5 = +bias -> split bf16 (Chi, Clo)          [QKV output]
// ---------------------------------------------------------------------------
#define BM 128
#define BN 128
#define BK 32
#define PA 40
#define PB 136
#define AS_ELEMS (BM * PA)
#define BS_ELEMS (BK * PB)
#define STAGE_ELEMS (2 * AS_ELEMS + 2 * BS_ELEMS)
#define GEMM_SMEM_BYTES (2 * STAGE_ELEMS * 2)      // 75776

template <int EPI>
__global__ __launch_bounds__(256, 2) void hgemm_kernel(
    const __nv_bfloat16* __restrict__ Ahi, const __nv_bfloat16* __restrict__ Alo,
    const __nv_bfloat16* __restrict__ Bhi, const __nv_bfloat16* __restrict__ Blo,
    const float* __restrict__ bias,
    float* __restrict__ C,
    __nv_bfloat16* __restrict__ Chi, __nv_bfloat16* __restrict__ Clo,
    int M, int N, int K)
{
    extern __shared__ __nv_bfloat16 sm[];
    const uint32_t smem_base = smem_u32(sm);
    const uint32_t stage_bytes = STAGE_ELEMS * 2;
    const uint32_t offAhi = 0;
    const uint32_t offAlo = AS_ELEMS * 2;
    const uint32_t offBhi = 2 * AS_ELEMS * 2;
    const uint32_t offBlo = (2 * AS_ELEMS + BS_ELEMS) * 2;

    const int tid  = threadIdx.x;
    const int lane = tid & 31;
    const int wid  = tid >> 5;
    const int warp_m = wid >> 1;
    const int warp_n = wid & 1;
    const int bm = blockIdx.y * BM;
    const int bn = blockIdx.x * BN;

    const int  Keff = (EPI == 4) ? (K / 3) : K;
    const int  kz   = (EPI == 4) ? (int)blockIdx.z : 0;
    const size_t kOff = (size_t)kz * Keff;
    float* Cout = (EPI == 4) ? (C + (size_t)kz * M * N) : C;

    const int a_row = tid >> 2;
    const int a_q   = tid & 3;
    const int b_row = tid >> 4;
    const int b_q   = tid & 15;

    float acc[2][8][4];
    #pragma unroll
    for (int i = 0; i < 2; i++)
        #pragma unroll
        for (int j = 0; j < 8; j++)
            #pragma unroll
            for (int t = 0; t < 4; t++) acc[i][j][t] = 0.f;

    const int n_tiles = Keff / BK;

    auto load_stage = [&](int s, int k0) {
        uint32_t base = smem_base + s * stage_bytes;
        #pragma unroll
        for (int j = 0; j < 2; j++) {
            int ar = a_row + j * 64;
            const __nv_bfloat16* srcA = Ahi + (size_t)(bm + ar) * K + kOff + k0 + a_q * 8;
            uint32_t dstA = base + offAhi + (ar * PA + a_q * 8) * 2;
            cp_async16(dstA, srcA);
            const __nv_bfloat16* srcAl = Alo + (size_t)(bm + ar) * K + kOff + k0 + a_q * 8;
            cp_async16(dstA + (offAlo - offAhi), srcAl);

            int br = b_row + j * 16;
            const __nv_bfloat16* srcB = Bhi + (kOff + (size_t)(k0 + br)) * N + bn + b_q * 8;
            uint32_t dstB = base + offBhi + (br * PB + b_q * 8) * 2;
            cp_async16(dstB, srcB);
            const __nv_bfloat16* srcBl = Blo + (kOff + (size_t)(k0 + br)) * N + bn + b_q * 8;
            cp_async16(dstB + (offBlo - offBhi), srcBl);
        }
    };

    load_stage(0, 0);
    cp_commit();

    const int lr = lane & 15;
    const int lc = (lane >> 4) * 8;

    for (int t = 0; t < n_tiles; t++) {
        int cur = t & 1;
        if (t + 1 < n_tiles) {
            load_stage((t + 1) & 1, (t + 1) * BK);
            cp_commit();
            cp_wait1();
        } else {
            cp_wait0();
        }
        __syncthreads();

        uint32_t base = smem_base + cur * stage_bytes;
        #pragma unroll
        for (int ks = 0; ks < BK; ks += 16) {
            uint32_t a_hi[2][4], a_lo[2][4];
            #pragma unroll
            for (int mi = 0; mi < 2; mi++) {
                uint32_t addr = base + offAhi +
                    ((warp_m * 32 + mi * 16 + lr) * PA + ks + lc) * 2;
                ldsm_x4(a_hi[mi], addr);
                ldsm_x4(a_lo[mi], addr + (offAlo - offAhi));
            }
            #pragma unroll
            for (int bi = 0; bi < 4; bi++) {
                uint32_t bh[4], bl[4];
                uint32_t addr = base + offBhi +
                    ((ks + lr) * PB + warp_n * 64 + bi * 16 + lc) * 2;
                ldsm_x4_t(bh, addr);
                ldsm_x4_t(bl, addr + (offBlo - offBhi));
                const int ni0 = bi * 2, ni1 = bi * 2 + 1;
                // term-major: 4 independent accs between same-acc repeats.
                // per-acc order stays hh -> hl -> lh (bit-identical).
                mma_bf16(acc[0][ni0], a_hi[0], bh[0], bh[1]);
                mma_bf16(acc[0][ni1], a_hi[0], bh[2], bh[3]);
                mma_bf16(acc[1][ni0], a_hi[1], bh[0], bh[1]);
                mma_bf16(acc[1][ni1], a_hi[1], bh[2], bh[3]);
                mma_bf16(acc[0][ni0], a_hi[0], bl[0], bl[1]);
                mma_bf16(acc[0][ni1], a_hi[0], bl[2], bl[3]);
                mma_bf16(acc[1][ni0], a_hi[1], bl[0], bl[1]);
                mma_bf16(acc[1][ni1], a_hi[1], bl[2], bl[3]);
                mma_bf16(acc[0][ni0], a_lo[0], bh[0], bh[1]);
                mma_bf16(acc[0][ni1], a_lo[0], bh[2], bh[3]);
                mma_bf16(acc[1][ni0], a_lo[1], bh[0], bh[1]);
                mma_bf16(acc[1][ni1], a_lo[1], bh[2], bh[3]);
            }
        }
        __syncthreads();
    }

    const int g = lane >> 2, tig = lane & 3;
    #pragma unroll
    for (int mi = 0; mi < 2; mi++) {
        #pragma unroll
        for (int ni = 0; ni < 8; ni++) {
            int r0 = bm + warp_m * 32 + mi * 16 + g;
            int r1 = r0 + 8;
            int c  = bn + warp_n * 64 + ni * 8 + tig * 2;
            float v00 = acc[mi][ni][0], v01 = acc[mi][ni][1];
            float v10 = acc[mi][ni][2], v11 = acc[mi][ni][3];
            if (EPI != 3 && EPI != 4) {
                float b0 = bias[c], b1 = bias[c + 1];
                v00 += b0; v01 += b1; v10 += b0; v11 += b1;
            }
            if (EPI == 1 || EPI == 5) {
                if (EPI == 1) {
                    v00 = gelu_exact(v00); v01 = gelu_exact(v01);
                    v10 = gelu_exact(v10); v11 = gelu_exact(v11);
                }
                split_store2(Chi, Clo, (size_t)r0 * N + c, v00, v01);
                split_store2(Chi, Clo, (size_t)r1 * N + c, v10, v11);
            } else {
                float2 o0 = make_float2(v00, v01);
                float2 o1 = make_float2(v10, v11);
                *(float2*)&Cout[(size_t)r0 * N + c] = o0;
                *(float2*)&Cout[(size_t)r1 * N + c] = o1;
            }
        }
    }
}

// ---------------------------------------------------------------------------
// Tensor-core flash attention, split-bf16 inputs via cp.async.
// One CTA (4 warps) per (b, h, 64-query tile); key tiles of 64.
// R15: S and Y MMA blocks interleaved across the j0/j1 accumulators.
// ---------------------------------------------------------------------------
#define ATT_TILE_B 8192                              // 64 x 128 B
#define ATT_SMEM_BYTES (6 * ATT_TILE_B + 256)        // 49408

__global__ __launch_bounds__(128) void attn_tc_kernel(
    const __nv_bfloat16* __restrict__ Qh_g, const __nv_bfloat16* __restrict__ Ql_g,
    const float* __restrict__ mask,
    __nv_bfloat16* __restrict__ Yhi, __nv_bfloat16* __restrict__ Ylo)
{
    extern __shared__ __nv_bfloat16 smb[];
    const uint32_t sb = smem_u32(smb);
    float* maskS = (float*)(smb + 6 * (ATT_TILE_B / 2));

    const uint32_t oK = 2 * ATT_TILE_B;   // Khi
    const uint32_t oV = 4 * ATT_TILE_B;   // Vhi
    const uint32_t dHL = ATT_TILE_B;      // hi -> lo byte offset

    const int b  = blockIdx.y / N_HEADS;
    const int h  = blockIdx.y % N_HEADS;
    const int qb = blockIdx.x * 64;
    const int tid = threadIdx.x, lane = tid & 31, w = tid >> 5;
    const size_t bT = (size_t)b * T_SEQ;

    // Q tile: 512 16B-chunks per buffer, 4 per thread (joins first commit group)
    #pragma unroll
    for (int i = 0; i < 4; i++) {
        int idx = tid + i * 128;
        int r = idx >> 3, cc = idx & 7;
        uint32_t dsw = (uint32_t)(r * 128 + ((cc << 4) ^ ((r & 7) << 4)));
        size_t src = (bT + qb + r) * NQKV + h * HD + cc * 8;
        cp_async16(sb + dsw,       Qh_g + src);
        cp_async16(sb + dHL + dsw, Ql_g + src);
    }

    float yacc[8][4];
    #pragma unroll
    for (int j = 0; j < 8; j++)
        #pragma unroll
        for (int t = 0; t < 4; t++) yacc[j][t] = 0.f;

    float m0 = -1e30f, m8 = -1e30f, l0 = 0.f, l8 = 0.f;
    const int g  = lane >> 2;
    const int c2 = (lane & 3) * 2;
    const int qrow0 = qb + w * 16 + g;
    const int qrow8 = qrow0 + 8;
    const int lr = lane & 15;
    const int hc = (lane >> 4);            // 0/1: high 16B chunk select

    for (int kb = 0; kb <= qb; kb += 64) {
        __syncthreads();   // previous tile's consumers done
        #pragma unroll
        for (int i = 0; i < 4; i++) {
            int idx = tid + i * 128;
            int r = idx >> 3, cc = idx & 7;
            uint32_t dsw = (uint32_t)(r * 128 + ((cc << 4) ^ ((r & 7) << 4)));
            size_t src = (bT + kb + r) * NQKV + h * HD + cc * 8;
            cp_async16(sb + oK + dsw,       Qh_g + P_PROJ + src);
            cp_async16(sb + oK + dHL + dsw, Ql_g + P_PROJ + src);
            cp_async16(sb + oV + dsw,       Qh_g + 2 * P_PROJ + src);
            cp_async16(sb + oV + dHL + dsw, Ql_g + 2 * P_PROJ + src);
        }
        cp_commit();
        if (tid < 64) maskS[tid] = mask[b * T_SEQ + kb + tid];
        cp_wait0();
        __syncthreads();

        // ---- S = Q K^T ----
        float sacc[8][4];
        #pragma unroll
        for (int j = 0; j < 8; j++)
            #pragma unroll
            for (int t = 0; t < 4; t++) sacc[j][t] = 0.f;

        #pragma unroll
        for (int ks = 0; ks < 4; ks++) {
            uint32_t ahi[4], alo[4];
            int ar = w * 16 + lr;
            int accc = ks * 2 + hc;
            uint32_t aaddr = sb + (uint32_t)(ar * 128 + ((accc << 4) ^ ((ar & 7) << 4)));
            ldsm_x4(ahi, aaddr);
            ldsm_x4(alo, aaddr + dHL);
            #pragma unroll
            for (int nb = 0; nb < 4; nb++) {
                uint32_t kh[4], kl[4];
                int kr = nb * 16 + lr;
                uint32_t kaddr = sb + oK + (uint32_t)(kr * 128 + ((accc << 4) ^ ((kr & 7) << 4)));
                ldsm_x4(kh, kaddr);
                ldsm_x4(kl, kaddr + dHL);
                int j0 = nb * 2, j1 = nb * 2 + 1;
                // term-major across the two accumulators (per-acc order kept)
                mma_bf16(sacc[j0], ahi, kh[0], kh[2]);
                mma_bf16(sacc[j1], ahi, kh[1], kh[3]);
                mma_bf16(sacc[j0], ahi, kl[0], kl[2]);
                mma_bf16(sacc[j1], ahi, kl[1], kl[3]);
                mma_bf16(sacc[j0], alo, kh[0], kh[2]);
                mma_bf16(sacc[j1], alo, kh[1], kh[3]);
            }
        }

        // ---- mask + online softmax ----
        float mx0 = -1e30f, mx8 = -1e30f;
        #pragma unroll
        for (int j = 0; j < 8; j++) {
            int k0 = kb + j * 8 + c2;
            float ms0 = maskS[j * 8 + c2], ms1 = maskS[j * 8 + c2 + 1];
            if (k0     > qrow0 || ms0 == 0.f) sacc[j][0] = -1e30f;
            if (k0 + 1 > qrow0 || ms1 == 0.f) sacc[j][1] = -1e30f;
            if (k0     > qrow8 || ms0 == 0.f) sacc[j][2] = -1e30f;
            if (k0 + 1 > qrow8 || ms1 == 0.f) sacc[j][3] = -1e30f;
            mx0 = fmaxf(mx0, fmaxf(sacc[j][0], sacc[j][1]));
            mx8 = fmaxf(mx8, fmaxf(sacc[j][2], sacc[j][3]));
        }
        mx0 = fmaxf(mx0, __shfl_xor_sync(0xffffffffu, mx0, 1));
        mx0 = fmaxf(mx0, __shfl_xor_sync(0xffffffffu, mx0, 2));
        mx8 = fmaxf(mx8, __shfl_xor_sync(0xffffffffu, mx8, 1));
        mx8 = fmaxf(mx8, __shfl_xor_sync(0xffffffffu, mx8, 2));

        float nm0 = fmaxf(m0, mx0), nm8 = fmaxf(m8, mx8);
        float corr0 = __expf(m0 - nm0), corr8 = __expf(m8 - nm8);
        m0 = nm0; m8 = nm8;

        float ps0 = 0.f, ps8 = 0.f;
        #pragma unroll
        for (int j = 0; j < 8; j++) {
            sacc[j][0] = __expf(sacc[j][0] - nm0);
            sacc[j][1] = __expf(sacc[j][1] - nm0);
            sacc[j][2] = __expf(sacc[j][2] - nm8);
            sacc[j][3] = __expf(sacc[j][3] - nm8);
            ps0 += sacc[j][0] + sacc[j][1];
            ps8 += sacc[j][2] + sacc[j][3];
        }
        ps0 += __shfl_xor_sync(0xffffffffu, ps0, 1);
        ps0 += __shfl_xor_sync(0xffffffffu, ps0, 2);
        ps8 += __shfl_xor_sync(0xffffffffu, ps8, 1);
        ps8 += __shfl_xor_sync(0xffffffffu, ps8, 2);
        l0 = l0 * corr0 + ps0;
        l8 = l8 * corr8 + ps8;

        #pragma unroll
        for (int j = 0; j < 8; j++) {
            yacc[j][0] *= corr0; yacc[j][1] *= corr0;
            yacc[j][2] *= corr8; yacc[j][3] *= corr8;
        }

        // ---- Y += P V ----
        #pragma unroll
        for (int kk = 0; kk < 4; kk++) {
            uint32_t phi[4], plo[4];
            pack_split(sacc[kk * 2][0],     sacc[kk * 2][1],     phi[0], plo[0]);
            pack_split(sacc[kk * 2][2],     sacc[kk * 2][3],     phi[1], plo[1]);
            pack_split(sacc[kk * 2 + 1][0], sacc[kk * 2 + 1][1], phi[2], plo[2]);
            pack_split(sacc[kk * 2 + 1][2], sacc[kk * 2 + 1][3], phi[3], plo[3]);
            #pragma unroll
            for (int nb = 0; nb < 4; nb++) {
                uint32_t vh[4], vl[4];
                int vr = kk * 16 + lr;
                int vcc = nb * 2 + hc;
                uint32_t vaddr = sb + oV + (uint32_t)(vr * 128 + ((vcc << 4) ^ ((vr & 7) << 4)));
                ldsm_x4_t(vh, vaddr);
                ldsm_x4_t(vl, vaddr + dHL);
                int j0 = nb * 2, j1 = nb * 2 + 1;
                // term-major across the two accumulators (per-acc order kept)
                mma_bf16(yacc[j0], phi, vh[0], vh[1]);
                mma_bf16(yacc[j1], phi, vh[2], vh[3]);
                mma_bf16(yacc[j0], phi, vl[0], vl[1]);
                mma_bf16(yacc[j1], phi, vl[2], vl[3]);
                mma_bf16(yacc[j0], plo, vh[0], vh[1]);
                mma_bf16(yacc[j1], plo, vh[2], vh[3]);
            }
        }
    }

    // ---- normalize + split-bf16 output ----
    float inv0 = 1.0f / l0, inv8 = 1.0f / l8;
    size_t row0 = (bT + qb + w * 16 + g) * P_PROJ + h * HD;
    size_t row8 = row0 + (size_t)8 * P_PROJ;
    #pragma unroll
    for (int j = 0; j < 8; j++) {
        int col = j * 8 + c2;
        split_store2(Yhi, Ylo, row0 + col, yacc[j][0] * inv0, yacc[j][1] * inv0);
        split_store2(Yhi, Ylo, row8 + col, yacc[j][2] * inv8, yacc[j][3] * inv8);
    }
}

// ---------------------------------------------------------------------------
// Host orchestration
// ---------------------------------------------------------------------------
static void split_launch(const float* src, __nv_bfloat16* hi, __nv_bfloat16* lo, int n) {
    int n4 = n / 4;
    split_kernel<<<(n4 + 255) / 256, 256>>>((const float4*)src, hi, lo, n4);
}

extern "C" void kernel_launch(void* const* d_in, const int* in_sizes, int n_in,
                              void* d_out, int out_size)
{
    const int*   idx       = (const int*)  d_in[0];
    const float* attn_mask = (const float*)d_in[1];
    const float* tok_emb   = (const float*)d_in[2];
    const float* pos_emb   = (const float*)d_in[3];
    const float* ln1_g     = (const float*)d_in[4];
    const float* ln1_b     = (const float*)d_in[5];
    const float* Wq        = (const float*)d_in[6];
    const float* bq        = (const float*)d_in[7];
    const float* Wk        = (const float*)d_in[8];
    const float* bk        = (const float*)d_in[9];
    const float* Wv        = (const float*)d_in[10];
    const float* bv        = (const float*)d_in[11];
    const float* Wo        = (const float*)d_in[12];
    const float* bo        = (const float*)d_in[13];
    const float* ln2_g     = (const float*)d_in[14];
    const float* ln2_b     = (const float*)d_in[15];
    const float* W1        = (const float*)d_in[16];
    const float* b1        = (const float*)d_in[17];
    const float* W2        = (const float*)d_in[18];
    const float* b2        = (const float*)d_in[19];
    const float* lnf_g     = (const float*)d_in[20];
    const float* lnf_b     = (const float*)d_in[21];
    const float* W_out     = (const float*)d_in[22];
    float* out = (float*)d_out;

    float *x, *bqkv, *part;
    __nv_bfloat16 *qkv_hi, *qkv_lo;
    __nv_bfloat16 *h_hi, *h_lo, *y_hi, *y_lo, *m1_hi, *m1_lo;
    __nv_bfloat16 *wqkv_hi, *wqkv_lo;
    __nv_bfloat16 *wo_hi, *wo_lo, *w1_hi, *w1_lo, *w2_hi, *w2_lo, *wout_hi, *wout_lo;

    cudaGetSymbolAddress((void**)&x,    g_x);
    cudaGetSymbolAddress((void**)&bqkv, g_bqkv);
    cudaGetSymbolAddress((void**)&part, g_part);
    cudaGetSymbolAddress((void**)&qkv_hi, g_qkv_hi);
    cudaGetSymbolAddress((void**)&qkv_lo, g_qkv_lo);
    cudaGetSymbolAddress((void**)&h_hi,  g_h_hi);
    cudaGetSymbolAddress((void**)&h_lo,  g_h_lo);
    cudaGetSymbolAddress((void**)&y_hi,  g_y_hi);
    cudaGetSymbolAddress((void**)&y_lo,  g_y_lo);
    cudaGetSymbolAddress((void**)&m1_hi, g_m1_hi);
    cudaGetSymbolAddress((void**)&m1_lo, g_m1_lo);
    cudaGetSymbolAddress((void**)&wqkv_hi, g_wqkv_hi);
    cudaGetSymbolAddress((void**)&wqkv_lo, g_wqkv_lo);
    cudaGetSymbolAddress((void**)&wo_hi, g_wo_hi);
    cudaGetSymbolAddress((void**)&wo_lo, g_wo_lo);
    cudaGetSymbolAddress((void**)&w1_hi, g_w1_hi);
    cudaGetSymbolAddress((void**)&w1_lo, g_w1_lo);
    cudaGetSymbolAddress((void**)&w2_hi, g_w2_hi);
    cudaGetSymbolAddress((void**)&w2_lo, g_w2_lo);
    cudaGetSymbolAddress((void**)&wout_hi, g_wout_hi);
    cudaGetSymbolAddress((void**)&wout_lo, g_wout_lo);

    cudaFuncSetAttribute(hgemm_kernel<1>, cudaFuncAttributeMaxDynamicSharedMemorySize, GEMM_SMEM_BYTES);
    cudaFuncSetAttribute(hgemm_kernel<3>, cudaFuncAttributeMaxDynamicSharedMemorySize, GEMM_SMEM_BYTES);
    cudaFuncSetAttribute(hgemm_kernel<4>, cudaFuncAttributeMaxDynamicSharedMemorySize, GEMM_SMEM_BYTES);
    cudaFuncSetAttribute(hgemm_kernel<5>, cudaFuncAttributeMaxDynamicSharedMemorySize, GEMM_SMEM_BYTES);
    cudaFuncSetAttribute(attn_tc_kernel,  cudaFuncAttributeMaxDynamicSharedMemorySize, ATT_SMEM_BYTES);

    const dim3 gqkv (NQKV / BN, ROWS / BM);          // (18, 64)
    const dim3 gsk  (P_PROJ / BN, ROWS / BM, 3);     // split-K x3 -> 1152 CTAs
    const dim3 gff  (FF_DIM / BN, ROWS / BM);        // (24, 64)
    const dim3 ghead(V_VOCAB / BN, ROWS / BM);       // (4, 64)
    const dim3 gattn(T_SEQ / 64, B_BATCH * N_HEADS); // (16, 96)
    const int  npack = (L_LAYERS * D_MODEL * (NQKV / 4) + 255) / 256;

    float* part0 = part;
    float* part1 = part + (size_t)ROWS * D_MODEL;
    float* part2 = part + (size_t)2 * ROWS * D_MODEL;

    // Launch order keeps ncu's sampled launch (index 3) = fused-QKV hgemm.
    embed_kernel<<<ROWS, 256>>>(idx, tok_emb, pos_emb, x);                               // 0
    layernorm_split_kernel<<<ROWS, 256>>>(x, ln1_g, ln1_b, h_hi, h_lo);                  // 1
    pack_qkv_kernel<<<npack, 256>>>(Wq, Wk, Wv, bq, bk, bv, wqkv_hi, wqkv_lo, bqkv);     // 2
    hgemm_kernel<5><<<gqkv, 256, GEMM_SMEM_BYTES>>>(                                     // 3 <- profiled
        h_hi, h_lo, wqkv_hi, wqkv_lo, bqkv,
        nullptr, qkv_hi, qkv_lo, ROWS, NQKV, D_MODEL);
    split_launch(Wo, wo_hi, wo_lo, L_LAYERS * P_PROJ * D_MODEL);                         // 4
    split_launch(W1, w1_hi, w1_lo, L_LAYERS * D_MODEL * FF_DIM);                         // 5
    split_launch(W2, w2_hi, w2_lo, L_LAYERS * FF_DIM * D_MODEL);                         // 6
    split_launch(W_out, wout_hi, wout_lo, D_MODEL * V_VOCAB);                            // 7

    for (int l = 0; l < L_LAYERS; l++) {
        const size_t wqkvo = (size_t)l * D_MODEL * NQKV;
        const size_t wdp   = (size_t)l * D_MODEL * P_PROJ;
        const size_t wdf   = (size_t)l * D_MODEL * FF_DIM;

        attn_tc_kernel<<<gattn, 128, ATT_SMEM_BYTES>>>(qkv_hi, qkv_lo, attn_mask, y_hi, y_lo);

        // part = y @ Wo (split-K x3); fused: x += part* + bo, h = LN2(x)
        hgemm_kernel<4><<<gsk, 256, GEMM_SMEM_BYTES>>>(
            y_hi, y_lo, wo_hi + wdp, wo_lo + wdp, nullptr,
            part, nullptr, nullptr, ROWS, D_MODEL, P_PROJ);
        ln_residual_split_kernel<<<ROWS, 256>>>(
            x, part0, part1, part2, bo + l * D_MODEL,
            ln2_g + l * D_MODEL, ln2_b + l * D_MODEL, h_hi, h_lo);

        // m1 = gelu(h @ W1 + b1) -> split bf16
        hgemm_kernel<1><<<gff, 256, GEMM_SMEM_BYTES>>>(
            h_hi, h_lo, w1_hi + wdf, w1_lo + wdf, b1 + l * FF_DIM,
            nullptr, m1_hi, m1_lo, ROWS, FF_DIM, D_MODEL);
        // part = m1 @ W2 (split-K x3); fused residual + next LN
        hgemm_kernel<4><<<gsk, 256, GEMM_SMEM_BYTES>>>(
            m1_hi, m1_lo, w2_hi + wdf, w2_lo + wdf, nullptr,
            part, nullptr, nullptr, ROWS, D_MODEL, FF_DIM);

        if (l + 1 < L_LAYERS) {
            ln_residual_split_kernel<<<ROWS, 256>>>(
                x, part0, part1, part2, b2 + l * D_MODEL,
                ln1_g + (l + 1) * D_MODEL, ln1_b + (l + 1) * D_MODEL, h_hi, h_lo);
            hgemm_kernel<5><<<gqkv, 256, GEMM_SMEM_BYTES>>>(
                h_hi, h_lo, wqkv_hi + wqkvo + (size_t)D_MODEL * NQKV,
                wqkv_lo + wqkvo + (size_t)D_MODEL * NQKV, bqkv + (l + 1) * NQKV,
                nullptr, qkv_hi, qkv_lo, ROWS, NQKV, D_MODEL);
        } else {
            ln_residual_split_kernel<<<ROWS, 256>>>(
                x, part0, part1, part2, b2 + l * D_MODEL,
                lnf_g, lnf_b, h_hi, h_lo);
        }
    }

    hgemm_kernel<3><<<ghead, 256, GEMM_SMEM_BYTES>>>(
        h_hi, h_lo, wout_hi, wout_lo, nullptr,
        out, nullptr, nullptr, ROWS, V_VOCAB, D_MODEL);
}

// round 16
// speedup vs baseline: 1.0341x; 1.0162x over previous
#include <cuda_runtime.h>
#include <cuda_bf16.h>
#include <math.h>
#include <stdint.h>

// ---------------------------------------------------------------------------
// Problem constants
// ---------------------------------------------------------------------------
#define L_LAYERS 6
#define V_VOCAB  512
#define D_MODEL  768
#define P_PROJ   768
#define N_HEADS  12
#define HD       64
#define FF_DIM   3072
#define B_BATCH  8
#define T_SEQ    1024
#define ROWS     (B_BATCH * T_SEQ)   // 8192
#define LN_EPS   1e-5f
#define NQKV     (3 * P_PROJ)        // 2304

// ---------------------------------------------------------------------------
// Scratch (device globals: allocation-free rule)
// ---------------------------------------------------------------------------
__device__ float g_x   [ROWS * D_MODEL];          // residual stream (fp32)
__device__ float g_part[3 * ROWS * D_MODEL];      // split-K partials (x3)

__device__ __nv_bfloat16 g_qkv_hi[ROWS * NQKV];   // fused q|k|v split bf16
__device__ __nv_bfloat16 g_qkv_lo[ROWS * NQKV];

__device__ __nv_bfloat16 g_h_hi [ROWS * D_MODEL];
__device__ __nv_bfloat16 g_h_lo [ROWS * D_MODEL];
__device__ __nv_bfloat16 g_y_hi [ROWS * P_PROJ];
__device__ __nv_bfloat16 g_y_lo [ROWS * P_PROJ];
__device__ __nv_bfloat16 g_m1_hi[ROWS * FF_DIM];
__device__ __nv_bfloat16 g_m1_lo[ROWS * FF_DIM];

// split weights ([K,N] row-major, as hgemm consumes them)
__device__ __nv_bfloat16 g_wqkv_hi[L_LAYERS * D_MODEL * NQKV];
__device__ __nv_bfloat16 g_wqkv_lo[L_LAYERS * D_MODEL * NQKV];
__device__ float         g_bqkv  [L_LAYERS * NQKV];
__device__ __nv_bfloat16 g_wo_hi[L_LAYERS * P_PROJ * D_MODEL];
__device__ __nv_bfloat16 g_wo_lo[L_LAYERS * P_PROJ * D_MODEL];
__device__ __nv_bfloat16 g_w1_hi[L_LAYERS * D_MODEL * FF_DIM];
__device__ __nv_bfloat16 g_w1_lo[L_LAYERS * D_MODEL * FF_DIM];
__device__ __nv_bfloat16 g_w2_hi[L_LAYERS * FF_DIM * D_MODEL];
__device__ __nv_bfloat16 g_w2_lo[L_LAYERS * FF_DIM * D_MODEL];
__device__ __nv_bfloat16 g_wout_hi[D_MODEL * V_VOCAB];
__device__ __nv_bfloat16 g_wout_lo[D_MODEL * V_VOCAB];

// ---------------------------------------------------------------------------
// Small helpers
// ---------------------------------------------------------------------------
__device__ __forceinline__ uint32_t smem_u32(const void* p) {
    return (uint32_t)__cvta_generic_to_shared(p);
}
__device__ __forceinline__ void cp_async16(uint32_t dst, const void* src) {
    asm volatile("cp.async.cg.shared.global [%0], [%1], 16;" :: "r"(dst), "l"(src));
}
__device__ __forceinline__ void cp_commit() {
    asm volatile("cp.async.commit_group;");
}
__device__ __forceinline__ void cp_wait1() {
    asm volatile("cp.async.wait_group 1;" ::: "memory");
}
__device__ __forceinline__ void cp_wait0() {
    asm volatile("cp.async.wait_group 0;" ::: "memory");
}
__device__ __forceinline__ void ldsm_x4(uint32_t* r, uint32_t addr) {
    asm volatile("ldmatrix.sync.aligned.m8n8.x4.shared.b16 {%0,%1,%2,%3}, [%4];"
                 : "=r"(r[0]), "=r"(r[1]), "=r"(r[2]), "=r"(r[3]) : "r"(addr));
}
__device__ __forceinline__ void ldsm_x4_t(uint32_t* r, uint32_t addr) {
    asm volatile("ldmatrix.sync.aligned.m8n8.x4.trans.shared.b16 {%0,%1,%2,%3}, [%4];"
                 : "=r"(r[0]), "=r"(r[1]), "=r"(r[2]), "=r"(r[3]) : "r"(addr));
}
__device__ __forceinline__ void mma_bf16(float* d, const uint32_t* a, uint32_t b0, uint32_t b1) {
    asm volatile("mma.sync.aligned.m16n8k16.row.col.f32.bf16.bf16.f32 "
                 "{%0,%1,%2,%3}, {%4,%5,%6,%7}, {%8,%9}, {%0,%1,%2,%3};"
                 : "+f"(d[0]), "+f"(d[1]), "+f"(d[2]), "+f"(d[3])
                 : "r"(a[0]), "r"(a[1]), "r"(a[2]), "r"(a[3]), "r"(b0), "r"(b1));
}
__device__ __forceinline__ float gelu_exact(float v) {
    return 0.5f * v * (1.0f + erff(v * 0.70710678118654752f));
}
__device__ __forceinline__ void split_store2(__nv_bfloat16* Hi, __nv_bfloat16* Lo,
                                             size_t off, float a, float b) {
    __nv_bfloat16 ha = __float2bfloat16(a), hb = __float2bfloat16(b);
    __nv_bfloat162 hv; hv.x = ha; hv.y = hb;
    *(__nv_bfloat162*)(Hi + off) = hv;
    __nv_bfloat162 lv;
    lv.x = __float2bfloat16(a - __bfloat162float(ha));
    lv.y = __float2bfloat16(b - __bfloat162float(hb));
    *(__nv_bfloat162*)(Lo + off) = lv;
}
// pack (a,b) into bf16x2 hi + bf16x2 lo registers (low 16 bits = a)
__device__ __forceinline__ void pack_split(float a, float b, uint32_t& hi, uint32_t& lo) {
    __nv_bfloat16 ha = __float2bfloat16(a), hb = __float2bfloat16(b);
    __nv_bfloat16 la = __float2bfloat16(a - __bfloat162float(ha));
    __nv_bfloat16 lb = __float2bfloat16(b - __bfloat162float(hb));
    hi = (uint32_t)__bfloat16_as_ushort(ha) | ((uint32_t)__bfloat16_as_ushort(hb) << 16);
    lo = (uint32_t)__bfloat16_as_ushort(la) | ((uint32_t)__bfloat16_as_ushort(lb) << 16);
}

// ---------------------------------------------------------------------------
// Weight split: fp32 -> (hi, lo) bf16, vectorized x4
// ---------------------------------------------------------------------------
__global__ void split_kernel(const float4* __restrict__ src,
                             __nv_bfloat16* __restrict__ hi,
                             __nv_bfloat16* __restrict__ lo, int n4)
{
    int i = blockIdx.x * 256 + threadIdx.x;
    if (i >= n4) return;
    float4 v = src[i];
    size_t off = (size_t)i * 4;
    split_store2(hi, lo, off,     v.x, v.y);
    split_store2(hi, lo, off + 2, v.z, v.w);
}

// ---------------------------------------------------------------------------
// Pack QKV weights+biases (vectorized float4). Wq/bq pre-scaled by 1/8 so the
// attention kernel needs no Q scaling.
// ---------------------------------------------------------------------------
__global__ __launch_bounds__(256) void pack_qkv_kernel(
    const float* __restrict__ Wq, const float* __restrict__ Wk,
    const float* __restrict__ Wv,
    const float* __restrict__ bq, const float* __restrict__ bk,
    const float* __restrict__ bv,
    __nv_bfloat16* __restrict__ Whi, __nv_bfloat16* __restrict__ Wlo,
    float* __restrict__ bias)
{
    const int NV4 = NQKV / 4;                          // 576
    int i = blockIdx.x * 256 + threadIdx.x;            // < L*D*NV4
    if (i >= L_LAYERS * D_MODEL * NV4) return;
    int n4  = i % NV4;
    int rem = i / NV4;
    int k   = rem % D_MODEL;
    int l   = rem / D_MODEL;
    int n   = n4 * 4;
    int sel = n / P_PROJ;
    int col = n % P_PROJ;
    const float sc = (sel == 0) ? 0.125f : 1.0f;
    const float* W = (sel == 0) ? Wq : (sel == 1) ? Wk : Wv;
    float4 v = *(const float4*)&W[((size_t)l * D_MODEL + k) * P_PROJ + col];
    v.x *= sc; v.y *= sc; v.z *= sc; v.w *= sc;
    size_t o = ((size_t)l * D_MODEL + k) * NQKV + n;
    split_store2(Whi, Wlo, o,     v.x, v.y);
    split_store2(Whi, Wlo, o + 2, v.z, v.w);
    if (k == 0) {
        const float* bb = (sel == 0) ? bq : (sel == 1) ? bk : bv;
        float4 bv4 = *(const float4*)&bb[l * P_PROJ + col];
        bv4.x *= sc; bv4.y *= sc; bv4.z *= sc; bv4.w *= sc;
        *(float4*)&bias[(size_t)l * NQKV + n] = bv4;
    }
}

// ---------------------------------------------------------------------------
// Embedding
// ---------------------------------------------------------------------------
__global__ void embed_kernel(const int* __restrict__ idx,
                             const float* __restrict__ tok,
                             const float* __restrict__ pos,
                             float* __restrict__ x)
{
    int r = blockIdx.x;
    int t = r & (T_SEQ - 1);
    int token = idx[r];
    const float* te = tok + (size_t)token * D_MODEL;
    const float* pe = pos + (size_t)t * D_MODEL;
    float* xr = x + (size_t)r * D_MODEL;
    for (int c = threadIdx.x; c < D_MODEL; c += 256)
        xr[c] = te[c] + pe[c];
}

// ---------------------------------------------------------------------------
// LayerNorm -> split bf16 (hi, lo)   (plain variant: layer-0 ln1)
// ---------------------------------------------------------------------------
__global__ __launch_bounds__(256) void layernorm_split_kernel(
    const float* __restrict__ x, const float* __restrict__ g,
    const float* __restrict__ b,
    __nv_bfloat16* __restrict__ ohi, __nv_bfloat16* __restrict__ olo)
{
    int row = blockIdx.x;
    const float* xr = x + (size_t)row * D_MODEL;
    int t = threadIdx.x;
    float v0 = xr[t], v1 = xr[t + 256], v2 = xr[t + 512];
    float s  = v0 + v1 + v2;
    float sq = v0 * v0 + v1 * v1 + v2 * v2;
    #pragma unroll
    for (int off = 16; off > 0; off >>= 1) {
        s  += __shfl_xor_sync(0xffffffffu, s,  off);
        sq += __shfl_xor_sync(0xffffffffu, sq, off);
    }
    __shared__ float ss[8], sqq[8];
    if ((t & 31) == 0) { ss[t >> 5] = s; sqq[t >> 5] = sq; }
    __syncthreads();
    float ts = 0.f, tsq = 0.f;
    #pragma unroll
    for (int i = 0; i < 8; i++) { ts += ss[i]; tsq += sqq[i]; }
    const float inv = 1.0f / (float)D_MODEL;
    float mu  = ts * inv;
    float var = tsq * inv - mu * mu;
    float r   = rsqrtf(var + LN_EPS);

    size_t base = (size_t)row * D_MODEL;
    #pragma unroll
    for (int i = 0; i < 3; i++) {
        int c = t + i * 256;
        float v = (i == 0 ? v0 : (i == 1 ? v1 : v2));
        float o = (v - mu) * r * g[c] + b[c];
        __nv_bfloat16 h = __float2bfloat16(o);
        ohi[base + c] = h;
        olo[base + c] = __float2bfloat16(o - __bfloat162float(h));
    }
}

// ---------------------------------------------------------------------------
// Fused split-K(x3) reduce + residual + LayerNorm -> split bf16.
// ---------------------------------------------------------------------------
__global__ __launch_bounds__(256) void ln_residual_split_kernel(
    float* __restrict__ x,
    const float* __restrict__ p0, const float* __restrict__ p1,
    const float* __restrict__ p2,
    const float* __restrict__ bias,
    const float* __restrict__ g, const float* __restrict__ b,
    __nv_bfloat16* __restrict__ ohi, __nv_bfloat16* __restrict__ olo)
{
    int row = blockIdx.x;
    size_t base = (size_t)row * D_MODEL;
    int t = threadIdx.x;

    float v0, v1, v2;
    {
        int c0 = t, c1 = t + 256, c2 = t + 512;
        v0 = x[base + c0] + p0[base + c0] + p1[base + c0] + p2[base + c0] + bias[c0];
        v1 = x[base + c1] + p0[base + c1] + p1[base + c1] + p2[base + c1] + bias[c1];
        v2 = x[base + c2] + p0[base + c2] + p1[base + c2] + p2[base + c2] + bias[c2];
        x[base + c0] = v0;
        x[base + c1] = v1;
        x[base + c2] = v2;
    }

    float s  = v0 + v1 + v2;
    float sq = v0 * v0 + v1 * v1 + v2 * v2;
    #pragma unroll
    for (int off = 16; off > 0; off >>= 1) {
        s  += __shfl_xor_sync(0xffffffffu, s,  off);
        sq += __shfl_xor_sync(0xffffffffu, sq, off);
    }
    __shared__ float ss[8], sqq[8];
    if ((t & 31) == 0) { ss[t >> 5] = s; sqq[t >> 5] = sq; }
    __syncthreads();
    float ts = 0.f, tsq = 0.f;
    #pragma unroll
    for (int i = 0; i < 8; i++) { ts += ss[i]; tsq += sqq[i]; }
    const float inv = 1.0f / (float)D_MODEL;
    float mu  = ts * inv;
    float var = tsq * inv - mu * mu;
    float r   = rsqrtf(var + LN_EPS);

    #pragma unroll
    for (int i = 0; i < 3; i++) {
        int c = t + i * 256;
        float v = (i == 0 ? v0 : (i == 1 ? v1 : v2));
        float o = (v - mu) * r * g[c] + b[c];
        __nv_bfloat16 h = __float2bfloat16(o);
        ohi[base + c] = h;
        olo[base + c] = __float2bfloat16(o - __bfloat162float(h));
    }
}

// ---------------------------------------------------------------------------
// Split-bf16 tensor-core GEMM. R16: CTA tile 64x128, 128 threads (4 warps,
// warp tile 32x64 unchanged), __launch_bounds__(128, 4) -> 4 independent
// CTAs/SM. Per-SM ldsm/MMA mix identical to the 128x128 version; the change
// desynchronizes barrier/epilogue phases across 4 schedules (R10 showed
// occupancy is the only lever that moved tensor%: 1->2 CTAs = 51.5->62.8%).
// K-accumulation order per output element unchanged -> bit-identical.
// EPI: 1 = +bias, exact GELU -> split bf16 (Chi, Clo)
//      3 = plain -> f32 C
//      4 = split-K partial (gridDim.z=3): z-th K-third -> C + z*M*N, f32
//      5 = +bias -> split bf16 (Chi, Clo)          [QKV output]
// ---------------------------------------------------------------------------
#define BM 64
#define BN 128
#define BK 32
#define PA 40
#define PB 136
#define AS_ELEMS (BM * PA)                         // 2560
#define BS_ELEMS (BK * PB)                         // 4352
#define STAGE_ELEMS (2 * AS_ELEMS + 2 * BS_ELEMS)  // 13824
#define GEMM_SMEM_BYTES (2 * STAGE_ELEMS * 2)      // 55296

template <int EPI>
__global__ __launch_bounds__(128, 4) void hgemm_kernel(
    const __nv_bfloat16* __restrict__ Ahi, const __nv_bfloat16* __restrict__ Alo,
    const __nv_bfloat16* __restrict__ Bhi, const __nv_bfloat16* __restrict__ Blo,
    const float* __restrict__ bias,
    float* __restrict__ C,
    __nv_bfloat16* __restrict__ Chi, __nv_bfloat16* __restrict__ Clo,
    int M, int N, int K)
{
    extern __shared__ __nv_bfloat16 sm[];
    const uint32_t smem_base = smem_u32(sm);
    const uint32_t stage_bytes = STAGE_ELEMS * 2;
    const uint32_t offAhi = 0;
    const uint32_t offAlo = AS_ELEMS * 2;
    const uint32_t offBhi = 2 * AS_ELEMS * 2;
    const uint32_t offBlo = (2 * AS_ELEMS + BS_ELEMS) * 2;

    const int tid  = threadIdx.x;
    const int lane = tid & 31;
    const int wid  = tid >> 5;            // 0..3
    const int warp_m = wid >> 1;          // 0..1
    const int warp_n = wid & 1;           // 0..1
    const int bm = blockIdx.y * BM;
    const int bn = blockIdx.x * BN;

    const int  Keff = (EPI == 4) ? (K / 3) : K;
    const int  kz   = (EPI == 4) ? (int)blockIdx.z : 0;
    const size_t kOff = (size_t)kz * Keff;
    float* Cout = (EPI == 4) ? (C + (size_t)kz * M * N) : C;

    // load mapping (128 threads):
    // A: row = tid>>1 (0..63), col half = (tid&1)*16 -> two 16B chunks
    // B: rows (tid>>4)+j*8 (j=0..3), col chunk = (tid&15)*8
    const int a_row = tid >> 1;
    const int a_q   = tid & 1;
    const int b_row = tid >> 4;           // 0..7
    const int b_q   = tid & 15;

    float acc[2][8][4];
    #pragma unroll
    for (int i = 0; i < 2; i++)
        #pragma unroll
        for (int j = 0; j < 8; j++)
            #pragma unroll
            for (int t = 0; t < 4; t++) acc[i][j][t] = 0.f;

    const int n_tiles = Keff / BK;

    auto load_stage = [&](int s, int k0) {
        uint32_t base = smem_base + s * stage_bytes;
        // A: 64 rows x 32 cols, hi+lo
        {
            const __nv_bfloat16* srcA = Ahi + (size_t)(bm + a_row) * K + kOff + k0 + a_q * 16;
            uint32_t dstA = base + offAhi + (a_row * PA + a_q * 16) * 2;
            cp_async16(dstA, srcA);
            cp_async16(dstA + 16, srcA + 8);
            const __nv_bfloat16* srcAl = Alo + (size_t)(bm + a_row) * K + kOff + k0 + a_q * 16;
            uint32_t dstAl = dstA + (offAlo - offAhi);
            cp_async16(dstAl, srcAl);
            cp_async16(dstAl + 16, srcAl + 8);
        }
        // B: 32 rows x 128 cols, hi+lo
        #pragma unroll
        for (int j = 0; j < 4; j++) {
            int br = b_row + j * 8;
            const __nv_bfloat16* srcB = Bhi + (kOff + (size_t)(k0 + br)) * N + bn + b_q * 8;
            uint32_t dstB = base + offBhi + (br * PB + b_q * 8) * 2;
            cp_async16(dstB, srcB);
            const __nv_bfloat16* srcBl = Blo + (kOff + (size_t)(k0 + br)) * N + bn + b_q * 8;
            cp_async16(dstB + (offBlo - offBhi), srcBl);
        }
    };

    load_stage(0, 0);
    cp_commit();

    const int lr = lane & 15;
    const int lc = (lane >> 4) * 8;

    for (int t = 0; t < n_tiles; t++) {
        int cur = t & 1;
        if (t + 1 < n_tiles) {
            load_stage((t + 1) & 1, (t + 1) * BK);
            cp_commit();
            cp_wait1();
        } else {
            cp_wait0();
        }
        __syncthreads();

        uint32_t base = smem_base + cur * stage_bytes;
        #pragma unroll
        for (int ks = 0; ks < BK; ks += 16) {
            uint32_t a_hi[2][4], a_lo[2][4];
            #pragma unroll
            for (int mi = 0; mi < 2; mi++) {
                uint32_t addr = base + offAhi +
                    ((warp_m * 32 + mi * 16 + lr) * PA + ks + lc) * 2;
                ldsm_x4(a_hi[mi], addr);
                ldsm_x4(a_lo[mi], addr + (offAlo - offAhi));
            }
            #pragma unroll
            for (int bi = 0; bi < 4; bi++) {
                uint32_t bh[4], bl[4];
                uint32_t addr = base + offBhi +
                    ((ks + lr) * PB + warp_n * 64 + bi * 16 + lc) * 2;
                ldsm_x4_t(bh, addr);
                ldsm_x4_t(bl, addr + (offBlo - offBhi));
                const int ni0 = bi * 2, ni1 = bi * 2 + 1;
                // term-major across independent accumulators; per-acc order
                // stays hh -> hl -> lh (bit-identical).
                mma_bf16(acc[0][ni0], a_hi[0], bh[0], bh[1]);
                mma_bf16(acc[0][ni1], a_hi[0], bh[2], bh[3]);
                mma_bf16(acc[1][ni0], a_hi[1], bh[0], bh[1]);
                mma_bf16(acc[1][ni1], a_hi[1], bh[2], bh[3]);
                mma_bf16(acc[0][ni0], a_hi[0], bl[0], bl[1]);
                mma_bf16(acc[0][ni1], a_hi[0], bl[2], bl[3]);
                mma_bf16(acc[1][ni0], a_hi[1], bl[0], bl[1]);
                mma_bf16(acc[1][ni1], a_hi[1], bl[2], bl[3]);
                mma_bf16(acc[0][ni0], a_lo[0], bh[0], bh[1]);
                mma_bf16(acc[0][ni1], a_lo[0], bh[2], bh[3]);
                mma_bf16(acc[1][ni0], a_lo[1], bh[0], bh[1]);
                mma_bf16(acc[1][ni1], a_lo[1], bh[2], bh[3]);
            }
        }
        __syncthreads();
    }

    const int g = lane >> 2, tig = lane & 3;
    #pragma unroll
    for (int mi = 0; mi < 2; mi++) {
        #pragma unroll
        for (int ni = 0; ni < 8; ni++) {
            int r0 = bm + warp_m * 32 + mi * 16 + g;
            int r1 = r0 + 8;
            int c  = bn + warp_n * 64 + ni * 8 + tig * 2;
            float v00 = acc[mi][ni][0], v01 = acc[mi][ni][1];
            float v10 = acc[mi][ni][2], v11 = acc[mi][ni][3];
            if (EPI != 3 && EPI != 4) {
                float b0 = bias[c], b1 = bias[c + 1];
                v00 += b0; v01 += b1; v10 += b0; v11 += b1;
            }
            if (EPI == 1 || EPI == 5) {
                if (EPI == 1) {
                    v00 = gelu_exact(v00); v01 = gelu_exact(v01);
                    v10 = gelu_exact(v10); v11 = gelu_exact(v11);
                }
                split_store2(Chi, Clo, (size_t)r0 * N + c, v00, v01);
                split_store2(Chi, Clo, (size_t)r1 * N + c, v10, v11);
            } else {
                float2 o0 = make_float2(v00, v01);
                float2 o1 = make_float2(v10, v11);
                *(float2*)&Cout[(size_t)r0 * N + c] = o0;
                *(float2*)&Cout[(size_t)r1 * N + c] = o1;
            }
        }
    }
}

// ---------------------------------------------------------------------------
// Tensor-core flash attention, split-bf16 inputs via cp.async.
// One CTA (4 warps) per (b, h, 64-query tile); key tiles of 64.
// R16: longest-qb-first CTA ordering (reverse blockIdx.x) for tail packing.
// ---------------------------------------------------------------------------
#define ATT_TILE_B 8192                              // 64 x 128 B
#define ATT_SMEM_BYTES (6 * ATT_TILE_B + 256)        // 49408

__global__ __launch_bounds__(128) void attn_tc_kernel(
    const __nv_bfloat16* __restrict__ Qh_g, const __nv_bfloat16* __restrict__ Ql_g,
    const float* __restrict__ mask,
    __nv_bfloat16* __restrict__ Yhi, __nv_bfloat16* __restrict__ Ylo)
{
    extern __shared__ __nv_bfloat16 smb[];
    const uint32_t sb = smem_u32(smb);
    float* maskS = (float*)(smb + 6 * (ATT_TILE_B / 2));

    const uint32_t oK = 2 * ATT_TILE_B;   // Khi
    const uint32_t oV = 4 * ATT_TILE_B;   // Vhi
    const uint32_t dHL = ATT_TILE_B;      // hi -> lo byte offset

    const int b  = blockIdx.y / N_HEADS;
    const int h  = blockIdx.y % N_HEADS;
    const int qb = (gridDim.x - 1 - blockIdx.x) * 64;   // long CTAs first
    const int tid = threadIdx.x, lane = tid & 31, w = tid >> 5;
    const size_t bT = (size_t)b * T_SEQ;

    // Q tile: 512 16B-chunks per buffer, 4 per thread (joins first commit group)
    #pragma unroll
    for (int i = 0; i < 4; i++) {
        int idx = tid + i * 128;
        int r = idx >> 3, cc = idx & 7;
        uint32_t dsw = (uint32_t)(r * 128 + ((cc << 4) ^ ((r & 7) << 4)));
        size_t src = (bT + qb + r) * NQKV + h * HD + cc * 8;
        cp_async16(sb + dsw,       Qh_g + src);
        cp_async16(sb + dHL + dsw, Ql_g + src);
    }

    float yacc[8][4];
    #pragma unroll
    for (int j = 0; j < 8; j++)
        #pragma unroll
        for (int t = 0; t < 4; t++) yacc[j][t] = 0.f;

    float m0 = -1e30f, m8 = -1e30f, l0 = 0.f, l8 = 0.f;
    const int g  = lane >> 2;
    const int c2 = (lane & 3) * 2;
    const int qrow0 = qb + w * 16 + g;
    const int qrow8 = qrow0 + 8;
    const int lr = lane & 15;
    const int hc = (lane >> 4);            // 0/1: high 16B chunk select

    for (int kb = 0; kb <= qb; kb += 64) {
        __syncthreads();   // previous tile's consumers done
        #pragma unroll
        for (int i = 0; i < 4; i++) {
            int idx = tid + i * 128;
            int r = idx >> 3, cc = idx & 7;
            uint32_t dsw = (uint32_t)(r * 128 + ((cc << 4) ^ ((r & 7) << 4)));
            size_t src = (bT + kb + r) * NQKV + h * HD + cc * 8;
            cp_async16(sb + oK + dsw,       Qh_g + P_PROJ + src);
            cp_async16(sb + oK + dHL + dsw, Ql_g + P_PROJ + src);
            cp_async16(sb + oV + dsw,       Qh_g + 2 * P_PROJ + src);
            cp_async16(sb + oV + dHL + dsw, Ql_g + 2 * P_PROJ + src);
        }
        cp_commit();
        if (tid < 64) maskS[tid] = mask[b * T_SEQ + kb + tid];
        cp_wait0();
        __syncthreads();

        // ---- S = Q K^T ----
        float sacc[8][4];
        #pragma unroll
        for (int j = 0; j < 8; j++)
            #pragma unroll
            for (int t = 0; t < 4; t++) sacc[j][t] = 0.f;

        #pragma unroll
        for (int ks = 0; ks < 4; ks++) {
            uint32_t ahi[4], alo[4];
            int ar = w * 16 + lr;
            int accc = ks * 2 + hc;
            uint32_t aaddr = sb + (uint32_t)(ar * 128 + ((accc << 4) ^ ((ar & 7) << 4)));
            ldsm_x4(ahi, aaddr);
            ldsm_x4(alo, aaddr + dHL);
            #pragma unroll
            for (int nb = 0; nb < 4; nb++) {
                uint32_t kh[4], kl[4];
                int kr = nb * 16 + lr;
                uint32_t kaddr = sb + oK + (uint32_t)(kr * 128 + ((accc << 4) ^ ((kr & 7) << 4)));
                ldsm_x4(kh, kaddr);
                ldsm_x4(kl, kaddr + dHL);
                int j0 = nb * 2, j1 = nb * 2 + 1;
                mma_bf16(sacc[j0], ahi, kh[0], kh[2]);
                mma_bf16(sacc[j1], ahi, kh[1], kh[3]);
                mma_bf16(sacc[j0], ahi, kl[0], kl[2]);
                mma_bf16(sacc[j1], ahi, kl[1], kl[3]);
                mma_bf16(sacc[j0], alo, kh[0], kh[2]);
                mma_bf16(sacc[j1], alo, kh[1], kh[3]);
            }
        }

        // ---- mask + online softmax ----
        float mx0 = -1e30f, mx8 = -1e30f;
        #pragma unroll
        for (int j = 0; j < 8; j++) {
            int k0 = kb + j * 8 + c2;
            float ms0 = maskS[j * 8 + c2], ms1 = maskS[j * 8 + c2 + 1];
            if (k0     > qrow0 || ms0 == 0.f) sacc[j][0] = -1e30f;
            if (k0 + 1 > qrow0 || ms1 == 0.f) sacc[j][1] = -1e30f;
            if (k0     > qrow8 || ms0 == 0.f) sacc[j][2] = -1e30f;
            if (k0 + 1 > qrow8 || ms1 == 0.f) sacc[j][3] = -1e30f;
            mx0 = fmaxf(mx0, fmaxf(sacc[j][0], sacc[j][1]));
            mx8 = fmaxf(mx8, fmaxf(sacc[j][2], sacc[j][3]));
        }
        mx0 = fmaxf(mx0, __shfl_xor_sync(0xffffffffu, mx0, 1));
        mx0 = fmaxf(mx0, __shfl_xor_sync(0xffffffffu, mx0, 2));
        mx8 = fmaxf(mx8, __shfl_xor_sync(0xffffffffu, mx8, 1));
        mx8 = fmaxf(mx8, __shfl_xor_sync(0xffffffffu, mx8, 2));

        float nm0 = fmaxf(m0, mx0), nm8 = fmaxf(m8, mx8);
        float corr0 = __expf(m0 - nm0), corr8 = __expf(m8 - nm8);
        m0 = nm0; m8 = nm8;

        float ps0 = 0.f, ps8 = 0.f;
        #pragma unroll
        for (int j = 0; j < 8; j++) {
            sacc[j][0] = __expf(sacc[j][0] - nm0);
            sacc[j][1] = __expf(sacc[j][1] - nm0);
            sacc[j][2] = __expf(sacc[j][2] - nm8);
            sacc[j][3] = __expf(sacc[j][3] - nm8);
            ps0 += sacc[j][0] + sacc[j][1];
            ps8 += sacc[j][2] + sacc[j][3];
        }
        ps0 += __shfl_xor_sync(0xffffffffu, ps0, 1);
        ps0 += __shfl_xor_sync(0xffffffffu, ps0, 2);
        ps8 += __shfl_xor_sync(0xffffffffu, ps8, 1);
        ps8 += __shfl_xor_sync(0xffffffffu, ps8, 2);
        l0 = l0 * corr0 + ps0;
        l8 = l8 * corr8 + ps8;

        #pragma unroll
        for (int j = 0; j < 8; j++) {
            yacc[j][0] *= corr0; yacc[j][1] *= corr0;
            yacc[j][2] *= corr8; yacc[j][3] *= corr8;
        }

        // ---- Y += P V ----
        #pragma unroll
        for (int kk = 0; kk < 4; kk++) {
            uint32_t phi[4], plo[4];
            pack_split(sacc[kk * 2][0],     sacc[kk * 2][1],     phi[0], plo[0]);
            pack_split(sacc[kk * 2][2],     sacc[kk * 2][3],     phi[1], plo[1]);
            pack_split(sacc[kk * 2 + 1][0], sacc[kk * 2 + 1][1], phi[2], plo[2]);
            pack_split(sacc[kk * 2 + 1][2], sacc[kk * 2 + 1][3], phi[3], plo[3]);
            #pragma unroll
            for (int nb = 0; nb < 4; nb++) {
                uint32_t vh[4], vl[4];
                int vr = kk * 16 + lr;
                int vcc = nb * 2 + hc;
                uint32_t vaddr = sb + oV + (uint32_t)(vr * 128 + ((vcc << 4) ^ ((vr & 7) << 4)));
                ldsm_x4_t(vh, vaddr);
                ldsm_x4_t(vl, vaddr + dHL);
                int j0 = nb * 2, j1 = nb * 2 + 1;
                mma_bf16(yacc[j0], phi, vh[0], vh[1]);
                mma_bf16(yacc[j1], phi, vh[2], vh[3]);
                mma_bf16(yacc[j0], phi, vl[0], vl[1]);
                mma_bf16(yacc[j1], phi, vl[2], vl[3]);
                mma_bf16(yacc[j0], plo, vh[0], vh[1]);
                mma_bf16(yacc[j1], plo, vh[2], vh[3]);
            }
        }
    }

    // ---- normalize + split-bf16 output ----
    float inv0 = 1.0f / l0, inv8 = 1.0f / l8;
    size_t row0 = (bT + qb + w * 16 + g) * P_PROJ + h * HD;
    size_t row8 = row0 + (size_t)8 * P_PROJ;
    #pragma unroll
    for (int j = 0; j < 8; j++) {
        int col = j * 8 + c2;
        split_store2(Yhi, Ylo, row0 + col, yacc[j][0] * inv0, yacc[j][1] * inv0);
        split_store2(Yhi, Ylo, row8 + col, yacc[j][2] * inv8, yacc[j][3] * inv8);
    }
}

// ---------------------------------------------------------------------------
// Host orchestration
// ---------------------------------------------------------------------------
static void split_launch(const float* src, __nv_bfloat16* hi, __nv_bfloat16* lo, int n) {
    int n4 = n / 4;
    split_kernel<<<(n4 + 255) / 256, 256>>>((const float4*)src, hi, lo, n4);
}

extern "C" void kernel_launch(void* const* d_in, const int* in_sizes, int n_in,
                              void* d_out, int out_size)
{
    const int*   idx       = (const int*)  d_in[0];
    const float* attn_mask = (const float*)d_in[1];
    const float* tok_emb   = (const float*)d_in[2];
    const float* pos_emb   = (const float*)d_in[3];
    const float* ln1_g     = (const float*)d_in[4];
    const float* ln1_b     = (const float*)d_in[5];
    const float* Wq        = (const float*)d_in[6];
    const float* bq        = (const float*)d_in[7];
    const float* Wk        = (const float*)d_in[8];
    const float* bk        = (const float*)d_in[9];
    const float* Wv        = (const float*)d_in[10];
    const float* bv        = (const float*)d_in[11];
    const float* Wo        = (const float*)d_in[12];
    const float* bo        = (const float*)d_in[13];
    const float* ln2_g     = (const float*)d_in[14];
    const float* ln2_b     = (const float*)d_in[15];
    const float* W1        = (const float*)d_in[16];
    const float* b1        = (const float*)d_in[17];
    const float* W2        = (const float*)d_in[18];
    const float* b2        = (const float*)d_in[19];
    const float* lnf_g     = (const float*)d_in[20];
    const float* lnf_b     = (const float*)d_in[21];
    const float* W_out     = (const float*)d_in[22];
    float* out = (float*)d_out;

    float *x, *bqkv, *part;
    __nv_bfloat16 *qkv_hi, *qkv_lo;
    __nv_bfloat16 *h_hi, *h_lo, *y_hi, *y_lo, *m1_hi, *m1_lo;
    __nv_bfloat16 *wqkv_hi, *wqkv_lo;
    __nv_bfloat16 *wo_hi, *wo_lo, *w1_hi, *w1_lo, *w2_hi, *w2_lo, *wout_hi, *wout_lo;

    cudaGetSymbolAddress((void**)&x,    g_x);
    cudaGetSymbolAddress((void**)&bqkv, g_bqkv);
    cudaGetSymbolAddress((void**)&part, g_part);
    cudaGetSymbolAddress((void**)&qkv_hi, g_qkv_hi);
    cudaGetSymbolAddress((void**)&qkv_lo, g_qkv_lo);
    cudaGetSymbolAddress((void**)&h_hi,  g_h_hi);
    cudaGetSymbolAddress((void**)&h_lo,  g_h_lo);
    cudaGetSymbolAddress((void**)&y_hi,  g_y_hi);
    cudaGetSymbolAddress((void**)&y_lo,  g_y_lo);
    cudaGetSymbolAddress((void**)&m1_hi, g_m1_hi);
    cudaGetSymbolAddress((void**)&m1_lo, g_m1_lo);
    cudaGetSymbolAddress((void**)&wqkv_hi, g_wqkv_hi);
    cudaGetSymbolAddress((void**)&wqkv_lo, g_wqkv_lo);
    cudaGetSymbolAddress((void**)&wo_hi, g_wo_hi);
    cudaGetSymbolAddress((void**)&wo_lo, g_wo_lo);
    cudaGetSymbolAddress((void**)&w1_hi, g_w1_hi);
    cudaGetSymbolAddress((void**)&w1_lo, g_w1_lo);
    cudaGetSymbolAddress((void**)&w2_hi, g_w2_hi);
    cudaGetSymbolAddress((void**)&w2_lo, g_w2_lo);
    cudaGetSymbolAddress((void**)&wout_hi, g_wout_hi);
    cudaGetSymbolAddress((void**)&wout_lo, g_wout_lo);

    cudaFuncSetAttribute(hgemm_kernel<1>, cudaFuncAttributeMaxDynamicSharedMemorySize, GEMM_SMEM_BYTES);
    cudaFuncSetAttribute(hgemm_kernel<3>, cudaFuncAttributeMaxDynamicSharedMemorySize, GEMM_SMEM_BYTES);
    cudaFuncSetAttribute(hgemm_kernel<4>, cudaFuncAttributeMaxDynamicSharedMemorySize, GEMM_SMEM_BYTES);
    cudaFuncSetAttribute(hgemm_kernel<5>, cudaFuncAttributeMaxDynamicSharedMemorySize, GEMM_SMEM_BYTES);
    cudaFuncSetAttribute(attn_tc_kernel,  cudaFuncAttributeMaxDynamicSharedMemorySize, ATT_SMEM_BYTES);

    const dim3 gqkv (NQKV / BN, ROWS / BM);          // (18, 128)
    const dim3 gsk  (P_PROJ / BN, ROWS / BM, 3);     // split-K x3 -> 2304 CTAs
    const dim3 gff  (FF_DIM / BN, ROWS / BM);        // (24, 128)
    const dim3 ghead(V_VOCAB / BN, ROWS / BM);       // (4, 128)
    const dim3 gattn(T_SEQ / 64, B_BATCH * N_HEADS); // (16, 96)
    const int  npack = (L_LAYERS * D_MODEL * (NQKV / 4) + 255) / 256;

    float* part0 = part;
    float* part1 = part + (size_t)ROWS * D_MODEL;
    float* part2 = part + (size_t)2 * ROWS * D_MODEL;

    // Launch order keeps ncu's sampled launch (index 3) = fused-QKV hgemm.
    embed_kernel<<<ROWS, 256>>>(idx, tok_emb, pos_emb, x);                               // 0
    layernorm_split_kernel<<<ROWS, 256>>>(x, ln1_g, ln1_b, h_hi, h_lo);                  // 1
    pack_qkv_kernel<<<npack, 256>>>(Wq, Wk, Wv, bq, bk, bv, wqkv_hi, wqkv_lo, bqkv);     // 2
    hgemm_kernel<5><<<gqkv, 128, GEMM_SMEM_BYTES>>>(                                     // 3 <- profiled
        h_hi, h_lo, wqkv_hi, wqkv_lo, bqkv,
        nullptr, qkv_hi, qkv_lo, ROWS, NQKV, D_MODEL);
    split_launch(Wo, wo_hi, wo_lo, L_LAYERS * P_PROJ * D_MODEL);                         // 4
    split_launch(W1, w1_hi, w1_lo, L_LAYERS * D_MODEL * FF_DIM);                         // 5
    split_launch(W2, w2_hi, w2_lo, L_LAYERS * FF_DIM * D_MODEL);                         // 6
    split_launch(W_out, wout_hi, wout_lo, D_MODEL * V_VOCAB);                            // 7

    for (int l = 0; l < L_LAYERS; l++) {
        const size_t wqkvo = (size_t)l * D_MODEL * NQKV;
        const size_t wdp   = (size_t)l * D_MODEL * P_PROJ;
        const size_t wdf   = (size_t)l * D_MODEL * FF_DIM;

        attn_tc_kernel<<<gattn, 128, ATT_SMEM_BYTES>>>(qkv_hi, qkv_lo, attn_mask, y_hi, y_lo);

        // part = y @ Wo (split-K x3); fused: x += part* + bo, h = LN2(x)
        hgemm_kernel<4><<<gsk, 128, GEMM_SMEM_BYTES>>>(
            y_hi, y_lo, wo_hi + wdp, wo_lo + wdp, nullptr,
            part, nullptr, nullptr, ROWS, D_MODEL, P_PROJ);
        ln_residual_split_kernel<<<ROWS, 256>>>(
            x, part0, part1, part2, bo + l * D_MODEL,
            ln2_g + l * D_MODEL, ln2_b + l * D_MODEL, h_hi, h_lo);

        // m1 = gelu(h @ W1 + b1) -> split bf16
        hgemm_kernel<1><<<gff, 128, GEMM_SMEM_BYTES>>>(
            h_hi, h_lo, w1_hi + wdf, w1_lo + wdf, b1 + l * FF_DIM,
            nullptr, m1_hi, m1_lo, ROWS, FF_DIM, D_MODEL);
        // part = m1 @ W2 (split-K x3); fused residual + next LN
        hgemm_kernel<4><<<gsk, 128, GEMM_SMEM_BYTES>>>(
            m1_hi, m1_lo, w2_hi + wdf, w2_lo + wdf, nullptr,
            part, nullptr, nullptr, ROWS, D_MODEL, FF_DIM);

        if (l + 1 < L_LAYERS) {
            ln_residual_split_kernel<<<ROWS, 256>>>(
                x, part0, part1, part2, b2 + l * D_MODEL,
                ln1_g + (l + 1) * D_MODEL, ln1_b + (l + 1) * D_MODEL, h_hi, h_lo);
            hgemm_kernel<5><<<gqkv, 128, GEMM_SMEM_BYTES>>>(
                h_hi, h_lo, wqkv_hi + wqkvo + (size_t)D_MODEL * NQKV,
                wqkv_lo + wqkvo + (size_t)D_MODEL * NQKV, bqkv + (l + 1) * NQKV,
                nullptr, qkv_hi, qkv_lo, ROWS, NQKV, D_MODEL);
        } else {
            ln_residual_split_kernel<<<ROWS, 256>>>(
                x, part0, part1, part2, b2 + l * D_MODEL,
                lnf_g, lnf_b, h_hi, h_lo);
        }
    }

    hgemm_kernel<3><<<ghead, 128, GEMM_SMEM_BYTES>>>(
        h_hi, h_lo, wout_hi, wout_lo, nullptr,
        out, nullptr, nullptr, ROWS, V_VOCAB, D_MODEL);
}

// round 17
// speedup vs baseline: 1.0360x; 1.0018x over previous
#include <cuda_runtime.h>
#include <cuda_bf16.h>
#include <math.h>
#include <stdint.h>

// ---------------------------------------------------------------------------
// Problem constants
// ---------------------------------------------------------------------------
#define L_LAYERS 6
#define V_VOCAB  512
#define D_MODEL  768
#define P_PROJ   768
#define N_HEADS  12
#define HD       64
#define FF_DIM   3072
#define B_BATCH  8
#define T_SEQ    1024
#define ROWS     (B_BATCH * T_SEQ)   // 8192
#define LN_EPS   1e-5f
#define NQKV     (3 * P_PROJ)        // 2304

// ---------------------------------------------------------------------------
// Scratch (device globals: allocation-free rule)
// ---------------------------------------------------------------------------
__device__ float g_x   [ROWS * D_MODEL];          // residual stream (fp32)
__device__ float g_part[3 * ROWS * D_MODEL];      // split-K partials (x3)

__device__ __nv_bfloat16 g_qkv_hi[ROWS * NQKV];   // fused q|k|v split bf16
__device__ __nv_bfloat16 g_qkv_lo[ROWS * NQKV];

__device__ __nv_bfloat16 g_h_hi [ROWS * D_MODEL];
__device__ __nv_bfloat16 g_h_lo [ROWS * D_MODEL];
__device__ __nv_bfloat16 g_y_hi [ROWS * P_PROJ];
__device__ __nv_bfloat16 g_y_lo [ROWS * P_PROJ];
__device__ __nv_bfloat16 g_m1_hi[ROWS * FF_DIM];
__device__ __nv_bfloat16 g_m1_lo[ROWS * FF_DIM];

// split weights ([K,N] row-major, as hgemm consumes them)
__device__ __nv_bfloat16 g_wqkv_hi[L_LAYERS * D_MODEL * NQKV];
__device__ __nv_bfloat16 g_wqkv_lo[L_LAYERS * D_MODEL * NQKV];
__device__ float         g_bqkv  [L_LAYERS * NQKV];
__device__ __nv_bfloat16 g_wo_hi[L_LAYERS * P_PROJ * D_MODEL];
__device__ __nv_bfloat16 g_wo_lo[L_LAYERS * P_PROJ * D_MODEL];
__device__ __nv_bfloat16 g_w1_hi[L_LAYERS * D_MODEL * FF_DIM];
__device__ __nv_bfloat16 g_w1_lo[L_LAYERS * D_MODEL * FF_DIM];
__device__ __nv_bfloat16 g_w2_hi[L_LAYERS * FF_DIM * D_MODEL];
__device__ __nv_bfloat16 g_w2_lo[L_LAYERS * FF_DIM * D_MODEL];
__device__ __nv_bfloat16 g_wout_hi[D_MODEL * V_VOCAB];
__device__ __nv_bfloat16 g_wout_lo[D_MODEL * V_VOCAB];

// ---------------------------------------------------------------------------
// Small helpers
// ---------------------------------------------------------------------------
__device__ __forceinline__ uint32_t smem_u32(const void* p) {
    return (uint32_t)__cvta_generic_to_shared(p);
}
__device__ __forceinline__ void cp_async16(uint32_t dst, const void* src) {
    asm volatile("cp.async.cg.shared.global [%0], [%1], 16;" :: "r"(dst), "l"(src));
}
__device__ __forceinline__ void cp_commit() {
    asm volatile("cp.async.commit_group;");
}
__device__ __forceinline__ void cp_wait1() {
    asm volatile("cp.async.wait_group 1;" ::: "memory");
}
__device__ __forceinline__ void cp_wait0() {
    asm volatile("cp.async.wait_group 0;" ::: "memory");
}
__device__ __forceinline__ void ldsm_x4(uint32_t* r, uint32_t addr) {
    asm volatile("ldmatrix.sync.aligned.m8n8.x4.shared.b16 {%0,%1,%2,%3}, [%4];"
                 : "=r"(r[0]), "=r"(r[1]), "=r"(r[2]), "=r"(r[3]) : "r"(addr));
}
__device__ __forceinline__ void ldsm_x4_t(uint32_t* r, uint32_t addr) {
    asm volatile("ldmatrix.sync.aligned.m8n8.x4.trans.shared.b16 {%0,%1,%2,%3}, [%4];"
                 : "=r"(r[0]), "=r"(r[1]), "=r"(r[2]), "=r"(r[3]) : "r"(addr));
}
__device__ __forceinline__ void mma_bf16(float* d, const uint32_t* a, uint32_t b0, uint32_t b1) {
    asm volatile("mma.sync.aligned.m16n8k16.row.col.f32.bf16.bf16.f32 "
                 "{%0,%1,%2,%3}, {%4,%5,%6,%7}, {%8,%9}, {%0,%1,%2,%3};"
                 : "+f"(d[0]), "+f"(d[1]), "+f"(d[2]), "+f"(d[3])
                 : "r"(a[0]), "r"(a[1]), "r"(a[2]), "r"(a[3]), "r"(b0), "r"(b1));
}
__device__ __forceinline__ float gelu_exact(float v) {
    return 0.5f * v * (1.0f + erff(v * 0.70710678118654752f));
}
__device__ __forceinline__ void split_store2(__nv_bfloat16* Hi, __nv_bfloat16* Lo,
                                             size_t off, float a, float b) {
    __nv_bfloat16 ha = __float2bfloat16(a), hb = __float2bfloat16(b);
    __nv_bfloat162 hv; hv.x = ha; hv.y = hb;
    *(__nv_bfloat162*)(Hi + off) = hv;
    __nv_bfloat162 lv;
    lv.x = __float2bfloat16(a - __bfloat162float(ha));
    lv.y = __float2bfloat16(b - __bfloat162float(hb));
    *(__nv_bfloat162*)(Lo + off) = lv;
}
// pack (a,b) into bf16x2 hi + bf16x2 lo registers (low 16 bits = a)
__device__ __forceinline__ void pack_split(float a, float b, uint32_t& hi, uint32_t& lo) {
    __nv_bfloat16 ha = __float2bfloat16(a), hb = __float2bfloat16(b);
    __nv_bfloat16 la = __float2bfloat16(a - __bfloat162float(ha));
    __nv_bfloat16 lb = __float2bfloat16(b - __bfloat162float(hb));
    hi = (uint32_t)__bfloat16_as_ushort(ha) | ((uint32_t)__bfloat16_as_ushort(hb) << 16);
    lo = (uint32_t)__bfloat16_as_ushort(la) | ((uint32_t)__bfloat16_as_ushort(lb) << 16);
}

// ---------------------------------------------------------------------------
// Weight split: fp32 -> (hi, lo) bf16, vectorized x4
// ---------------------------------------------------------------------------
__global__ void split_kernel(const float4* __restrict__ src,
                             __nv_bfloat16* __restrict__ hi,
                             __nv_bfloat16* __restrict__ lo, int n4)
{
    int i = blockIdx.x * 256 + threadIdx.x;
    if (i >= n4) return;
    float4 v = src[i];
    size_t off = (size_t)i * 4;
    split_store2(hi, lo, off,     v.x, v.y);
    split_store2(hi, lo, off + 2, v.z, v.w);
}

// ---------------------------------------------------------------------------
// Pack QKV weights+biases (vectorized float4). Wq/bq pre-scaled by 1/8 so the
// attention kernel needs no Q scaling.
// ---------------------------------------------------------------------------
__global__ __launch_bounds__(256) void pack_qkv_kernel(
    const float* __restrict__ Wq, const float* __restrict__ Wk,
    const float* __restrict__ Wv,
    const float* __restrict__ bq, const float* __restrict__ bk,
    const float* __restrict__ bv,
    __nv_bfloat16* __restrict__ Whi, __nv_bfloat16* __restrict__ Wlo,
    float* __restrict__ bias)
{
    const int NV4 = NQKV / 4;                          // 576
    int i = blockIdx.x * 256 + threadIdx.x;            // < L*D*NV4
    if (i >= L_LAYERS * D_MODEL * NV4) return;
    int n4  = i % NV4;
    int rem = i / NV4;
    int k   = rem % D_MODEL;
    int l   = rem / D_MODEL;
    int n   = n4 * 4;
    int sel = n / P_PROJ;
    int col = n % P_PROJ;
    const float sc = (sel == 0) ? 0.125f : 1.0f;
    const float* W = (sel == 0) ? Wq : (sel == 1) ? Wk : Wv;
    float4 v = *(const float4*)&W[((size_t)l * D_MODEL + k) * P_PROJ + col];
    v.x *= sc; v.y *= sc; v.z *= sc; v.w *= sc;
    size_t o = ((size_t)l * D_MODEL + k) * NQKV + n;
    split_store2(Whi, Wlo, o,     v.x, v.y);
    split_store2(Whi, Wlo, o + 2, v.z, v.w);
    if (k == 0) {
        const float* bb = (sel == 0) ? bq : (sel == 1) ? bk : bv;
        float4 bv4 = *(const float4*)&bb[l * P_PROJ + col];
        bv4.x *= sc; bv4.y *= sc; bv4.z *= sc; bv4.w *= sc;
        *(float4*)&bias[(size_t)l * NQKV + n] = bv4;
    }
}

// ---------------------------------------------------------------------------
// Embedding
// ---------------------------------------------------------------------------
__global__ void embed_kernel(const int* __restrict__ idx,
                             const float* __restrict__ tok,
                             const float* __restrict__ pos,
                             float* __restrict__ x)
{
    int r = blockIdx.x;
    int t = r & (T_SEQ - 1);
    int token = idx[r];
    const float* te = tok + (size_t)token * D_MODEL;
    const float* pe = pos + (size_t)t * D_MODEL;
    float* xr = x + (size_t)r * D_MODEL;
    for (int c = threadIdx.x; c < D_MODEL; c += 256)
        xr[c] = te[c] + pe[c];
}

// ---------------------------------------------------------------------------
// LayerNorm -> split bf16 (hi, lo)   (plain variant: layer-0 ln1)
// ---------------------------------------------------------------------------
__global__ __launch_bounds__(256) void layernorm_split_kernel(
    const float* __restrict__ x, const float* __restrict__ g,
    const float* __restrict__ b,
    __nv_bfloat16* __restrict__ ohi, __nv_bfloat16* __restrict__ olo)
{
    int row = blockIdx.x;
    const float* xr = x + (size_t)row * D_MODEL;
    int t = threadIdx.x;
    float v0 = xr[t], v1 = xr[t + 256], v2 = xr[t + 512];
    float s  = v0 + v1 + v2;
    float sq = v0 * v0 + v1 * v1 + v2 * v2;
    #pragma unroll
    for (int off = 16; off > 0; off >>= 1) {
        s  += __shfl_xor_sync(0xffffffffu, s,  off);
        sq += __shfl_xor_sync(0xffffffffu, sq, off);
    }
    __shared__ float ss[8], sqq[8];
    if ((t & 31) == 0) { ss[t >> 5] = s; sqq[t >> 5] = sq; }
    __syncthreads();
    float ts = 0.f, tsq = 0.f;
    #pragma unroll
    for (int i = 0; i < 8; i++) { ts += ss[i]; tsq += sqq[i]; }
    const float inv = 1.0f / (float)D_MODEL;
    float mu  = ts * inv;
    float var = tsq * inv - mu * mu;
    float r   = rsqrtf(var + LN_EPS);

    size_t base = (size_t)row * D_MODEL;
    #pragma unroll
    for (int i = 0; i < 3; i++) {
        int c = t + i * 256;
        float v = (i == 0 ? v0 : (i == 1 ? v1 : v2));
        float o = (v - mu) * r * g[c] + b[c];
        __nv_bfloat16 h = __float2bfloat16(o);
        ohi[base + c] = h;
        olo[base + c] = __float2bfloat16(o - __bfloat162float(h));
    }
}

// ---------------------------------------------------------------------------
// Fused split-K(x3) reduce + residual + LayerNorm -> split bf16.
// ---------------------------------------------------------------------------
__global__ __launch_bounds__(256) void ln_residual_split_kernel(
    float* __restrict__ x,
    const float* __restrict__ p0, const float* __restrict__ p1,
    const float* __restrict__ p2,
    const float* __restrict__ bias,
    const float* __restrict__ g, const float* __restrict__ b,
    __nv_bfloat16* __restrict__ ohi, __nv_bfloat16* __restrict__ olo)
{
    int row = blockIdx.x;
    size_t base = (size_t)row * D_MODEL;
    int t = threadIdx.x;

    float v0, v1, v2;
    {
        int c0 = t, c1 = t + 256, c2 = t + 512;
        v0 = x[base + c0] + p0[base + c0] + p1[base + c0] + p2[base + c0] + bias[c0];
        v1 = x[base + c1] + p0[base + c1] + p1[base + c1] + p2[base + c1] + bias[c1];
        v2 = x[base + c2] + p0[base + c2] + p1[base + c2] + p2[base + c2] + bias[c2];
        x[base + c0] = v0;
        x[base + c1] = v1;
        x[base + c2] = v2;
    }

    float s  = v0 + v1 + v2;
    float sq = v0 * v0 + v1 * v1 + v2 * v2;
    #pragma unroll
    for (int off = 16; off > 0; off >>= 1) {
        s  += __shfl_xor_sync(0xffffffffu, s,  off);
        sq += __shfl_xor_sync(0xffffffffu, sq, off);
    }
    __shared__ float ss[8], sqq[8];
    if ((t & 31) == 0) { ss[t >> 5] = s; sqq[t >> 5] = sq; }
    __syncthreads();
    float ts = 0.f, tsq = 0.f;
    #pragma unroll
    for (int i = 0; i < 8; i++) { ts += ss[i]; tsq += sqq[i]; }
    const float inv = 1.0f / (float)D_MODEL;
    float mu  = ts * inv;
    float var = tsq * inv - mu * mu;
    float r   = rsqrtf(var + LN_EPS);

    #pragma unroll
    for (int i = 0; i < 3; i++) {
        int c = t + i * 256;
        float v = (i == 0 ? v0 : (i == 1 ? v1 : v2));
        float o = (v - mu) * r * g[c] + b[c];
        __nv_bfloat16 h = __float2bfloat16(o);
        ohi[base + c] = h;
        olo[base + c] = __float2bfloat16(o - __bfloat162float(h));
    }
}

// ---------------------------------------------------------------------------
// Split-bf16 tensor-core GEMM. R16: CTA tile 64x128, 128 threads (4 warps,
// warp tile 32x64 unchanged), __launch_bounds__(128, 4) -> 4 independent
// CTAs/SM. Per-SM ldsm/MMA mix identical to the 128x128 version; the change
// desynchronizes barrier/epilogue phases across 4 schedules (R10 showed
// occupancy is the only lever that moved tensor%: 1->2 CTAs = 51.5->62.8%).
// K-accumulation order per output element unchanged -> bit-identical.
// EPI: 1 = +bias, exact GELU -> split bf16 (Chi, Clo)
//      3 = plain -> f32 C
//      4 = split-K partial (gridDim.z=3): z-th K-third -> C + z*M*N, f32
//      5 = +bias -> split bf16 (Chi, Clo)          [QKV output]
// ---------------------------------------------------------------------------
#define BM 64
#define BN 128
#define BK 32
#define PA 40
#define PB 136
#define AS_ELEMS (BM * PA)                         // 2560
#define BS_ELEMS (BK * PB)                         // 4352
#define STAGE_ELEMS (2 * AS_ELEMS + 2 * BS_ELEMS)  // 13824
#define GEMM_SMEM_BYTES (2 * STAGE_ELEMS * 2)      // 55296

template <int EPI>
__global__ __launch_bounds__(128, 4) void hgemm_kernel(
    const __nv_bfloat16* __restrict__ Ahi, const __nv_bfloat16* __restrict__ Alo,
    const __nv_bfloat16* __restrict__ Bhi, const __nv_bfloat16* __restrict__ Blo,
    const float* __restrict__ bias,
    float* __restrict__ C,
    __nv_bfloat16* __restrict__ Chi, __nv_bfloat16* __restrict__ Clo,
    int M, int N, int K)
{
    extern __shared__ __nv_bfloat16 sm[];
    const uint32_t smem_base = smem_u32(sm);
    const uint32_t stage_bytes = STAGE_ELEMS * 2;
    const uint32_t offAhi = 0;
    const uint32_t offAlo = AS_ELEMS * 2;
    const uint32_t offBhi = 2 * AS_ELEMS * 2;
    const uint32_t offBlo = (2 * AS_ELEMS + BS_ELEMS) * 2;

    const int tid  = threadIdx.x;
    const int lane = tid & 31;
    const int wid  = tid >> 5;            // 0..3
    const int warp_m = wid >> 1;          // 0..1
    const int warp_n = wid & 1;           // 0..1
    const int bm = blockIdx.y * BM;
    const int bn = blockIdx.x * BN;

    const int  Keff = (EPI == 4) ? (K / 3) : K;
    const int  kz   = (EPI == 4) ? (int)blockIdx.z : 0;
    const size_t kOff = (size_t)kz * Keff;
    float* Cout = (EPI == 4) ? (C + (size_t)kz * M * N) : C;

    // load mapping (128 threads):
    // A: row = tid>>1 (0..63), col half = (tid&1)*16 -> two 16B chunks
    // B: rows (tid>>4)+j*8 (j=0..3), col chunk = (tid&15)*8
    const int a_row = tid >> 1;
    const int a_q   = tid & 1;
    const int b_row = tid >> 4;           // 0..7
    const int b_q   = tid & 15;

    float acc[2][8][4];
    #pragma unroll
    for (int i = 0; i < 2; i++)
        #pragma unroll
        for (int j = 0; j < 8; j++)
            #pragma unroll
            for (int t = 0; t < 4; t++) acc[i][j][t] = 0.f;

    const int n_tiles = Keff / BK;

    auto load_stage = [&](int s, int k0) {
        uint32_t base = smem_base + s * stage_bytes;
        // A: 64 rows x 32 cols, hi+lo
        {
            const __nv_bfloat16* srcA = Ahi + (size_t)(bm + a_row) * K + kOff + k0 + a_q * 16;
            uint32_t dstA = base + offAhi + (a_row * PA + a_q * 16) * 2;
            cp_async16(dstA, srcA);
            cp_async16(dstA + 16, srcA + 8);
            const __nv_bfloat16* srcAl = Alo + (size_t)(bm + a_row) * K + kOff + k0 + a_q * 16;
            uint32_t dstAl = dstA + (offAlo - offAhi);
            cp_async16(dstAl, srcAl);
            cp_async16(dstAl + 16, srcAl + 8);
        }
        // B: 32 rows x 128 cols, hi+lo
        #pragma unroll
        for (int j = 0; j < 4; j++) {
            int br = b_row + j * 8;
            const __nv_bfloat16* srcB = Bhi + (kOff + (size_t)(k0 + br)) * N + bn + b_q * 8;
            uint32_t dstB = base + offBhi + (br * PB + b_q * 8) * 2;
            cp_async16(dstB, srcB);
            const __nv_bfloat16* srcBl = Blo + (kOff + (size_t)(k0 + br)) * N + bn + b_q * 8;
            cp_async16(dstB + (offBlo - offBhi), srcBl);
        }
    };

    load_stage(0, 0);
    cp_commit();

    const int lr = lane & 15;
    const int lc = (lane >> 4) * 8;

    for (int t = 0; t < n_tiles; t++) {
        int cur = t & 1;
        if (t + 1 < n_tiles) {
            load_stage((t + 1) & 1, (t + 1) * BK);
            cp_commit();
            cp_wait1();
        } else {
            cp_wait0();
        }
        __syncthreads();

        uint32_t base = smem_base + cur * stage_bytes;
        #pragma unroll
        for (int ks = 0; ks < BK; ks += 16) {
            uint32_t a_hi[2][4], a_lo[2][4];
            #pragma unroll
            for (int mi = 0; mi < 2; mi++) {
                uint32_t addr = base + offAhi +
                    ((warp_m * 32 + mi * 16 + lr) * PA + ks + lc) * 2;
                ldsm_x4(a_hi[mi], addr);
                ldsm_x4(a_lo[mi], addr + (offAlo - offAhi));
            }
            #pragma unroll
            for (int bi = 0; bi < 4; bi++) {
                uint32_t bh[4], bl[4];
                uint32_t addr = base + offBhi +
                    ((ks + lr) * PB + warp_n * 64 + bi * 16 + lc) * 2;
                ldsm_x4_t(bh, addr);
                ldsm_x4_t(bl, addr + (offBlo - offBhi));
                const int ni0 = bi * 2, ni1 = bi * 2 + 1;
                // term-major across independent accumulators; per-acc order
                // stays hh -> hl -> lh (bit-identical).
                mma_bf16(acc[0][ni0], a_hi[0], bh[0], bh[1]);
                mma_bf16(acc[0][ni1], a_hi[0], bh[2], bh[3]);
                mma_bf16(acc[1][ni0], a_hi[1], bh[0], bh[1]);
                mma_bf16(acc[1][ni1], a_hi[1], bh[2], bh[3]);
                mma_bf16(acc[0][ni0], a_hi[0], bl[0], bl[1]);
                mma_bf16(acc[0][ni1], a_hi[0], bl[2], bl[3]);
                mma_bf16(acc[1][ni0], a_hi[1], bl[0], bl[1]);
                mma_bf16(acc[1][ni1], a_hi[1], bl[2], bl[3]);
                mma_bf16(acc[0][ni0], a_lo[0], bh[0], bh[1]);
                mma_bf16(acc[0][ni1], a_lo[0], bh[2], bh[3]);
                mma_bf16(acc[1][ni0], a_lo[1], bh[0], bh[1]);
                mma_bf16(acc[1][ni1], a_lo[1], bh[2], bh[3]);
            }
        }
        __syncthreads();
    }

    const int g = lane >> 2, tig = lane & 3;
    #pragma unroll
    for (int mi = 0; mi < 2; mi++) {
        #pragma unroll
        for (int ni = 0; ni < 8; ni++) {
            int r0 = bm + warp_m * 32 + mi * 16 + g;
            int r1 = r0 + 8;
            int c  = bn + warp_n * 64 + ni * 8 + tig * 2;
            float v00 = acc[mi][ni][0], v01 = acc[mi][ni][1];
            float v10 = acc[mi][ni][2], v11 = acc[mi][ni][3];
            if (EPI != 3 && EPI != 4) {
                float b0 = bias[c], b1 = bias[c + 1];
                v00 += b0; v01 += b1; v10 += b0; v11 += b1;
            }
            if (EPI == 1 || EPI == 5) {
                if (EPI == 1) {
                    v00 = gelu_exact(v00); v01 = gelu_exact(v01);
                    v10 = gelu_exact(v10); v11 = gelu_exact(v11);
                }
                split_store2(Chi, Clo, (size_t)r0 * N + c, v00, v01);
                split_store2(Chi, Clo, (size_t)r1 * N + c, v10, v11);
            } else {
                float2 o0 = make_float2(v00, v01);
                float2 o1 = make_float2(v10, v11);
                *(float2*)&Cout[(size_t)r0 * N + c] = o0;
                *(float2*)&Cout[(size_t)r1 * N + c] = o1;
            }
        }
    }
}

// ---------------------------------------------------------------------------
// Tensor-core flash attention, split-bf16 inputs via cp.async.
// One CTA (4 warps) per (b, h, 64-query tile); key tiles of 64.
// R16: longest-qb-first CTA ordering (reverse blockIdx.x) for tail packing.
// ---------------------------------------------------------------------------
#define ATT_TILE_B 8192                              // 64 x 128 B
#define ATT_SMEM_BYTES (6 * ATT_TILE_B + 256)        // 49408

__global__ __launch_bounds__(128) void attn_tc_kernel(
    const __nv_bfloat16* __restrict__ Qh_g, const __nv_bfloat16* __restrict__ Ql_g,
    const float* __restrict__ mask,
    __nv_bfloat16* __restrict__ Yhi, __nv_bfloat16* __restrict__ Ylo)
{
    extern __shared__ __nv_bfloat16 smb[];
    const uint32_t sb = smem_u32(smb);
    float* maskS = (float*)(smb + 6 * (ATT_TILE_B / 2));

    const uint32_t oK = 2 * ATT_TILE_B;   // Khi
    const uint32_t oV = 4 * ATT_TILE_B;   // Vhi
    const uint32_t dHL = ATT_TILE_B;      // hi -> lo byte offset

    const int b  = blockIdx.y / N_HEADS;
    const int h  = blockIdx.y % N_HEADS;
    const int qb = (gridDim.x - 1 - blockIdx.x) * 64;   // long CTAs first
    const int tid = threadIdx.x, lane = tid & 31, w = tid >> 5;
    const size_t bT = (size_t)b * T_SEQ;

    // Q tile: 512 16B-chunks per buffer, 4 per thread (joins first commit group)
    #pragma unroll
    for (int i = 0; i < 4; i++) {
        int idx = tid + i * 128;
        int r = idx >> 3, cc = idx & 7;
        uint32_t dsw = (uint32_t)(r * 128 + ((cc << 4) ^ ((r & 7) << 4)));
        size_t src = (bT + qb + r) * NQKV + h * HD + cc * 8;
        cp_async16(sb + dsw,       Qh_g + src);
        cp_async16(sb + dHL + dsw, Ql_g + src);
    }

    float yacc[8][4];
    #pragma unroll
    for (int j = 0; j < 8; j++)
        #pragma unroll
        for (int t = 0; t < 4; t++) yacc[j][t] = 0.f;

    float m0 = -1e30f, m8 = -1e30f, l0 = 0.f, l8 = 0.f;
    const int g  = lane >> 2;
    const int c2 = (lane & 3) * 2;
    const int qrow0 = qb + w * 16 + g;
    const int qrow8 = qrow0 + 8;
    const int lr = lane & 15;
    const int hc = (lane >> 4);            // 0/1: high 16B chunk select

    for (int kb = 0; kb <= qb; kb += 64) {
        __syncthreads();   // previous tile's consumers done
        #pragma unroll
        for (int i = 0; i < 4; i++) {
            int idx = tid + i * 128;
            int r = idx >> 3, cc = idx & 7;
            uint32_t dsw = (uint32_t)(r * 128 + ((cc << 4) ^ ((r & 7) << 4)));
            size_t src = (bT + kb + r) * NQKV + h * HD + cc * 8;
            cp_async16(sb + oK + dsw,       Qh_g + P_PROJ + src);
            cp_async16(sb + oK + dHL + dsw, Ql_g + P_PROJ + src);
            cp_async16(sb + oV + dsw,       Qh_g + 2 * P_PROJ + src);
            cp_async16(sb + oV + dHL + dsw, Ql_g + 2 * P_PROJ + src);
        }
        cp_commit();
        if (tid < 64) maskS[tid] = mask[b * T_SEQ + kb + tid];
        cp_wait0();
        __syncthreads();

        // ---- S = Q K^T ----
        float sacc[8][4];
        #pragma unroll
        for (int j = 0; j < 8; j++)
            #pragma unroll
            for (int t = 0; t < 4; t++) sacc[j][t] = 0.f;

        #pragma unroll
        for (int ks = 0; ks < 4; ks++) {
            uint32_t ahi[4], alo[4];
            int ar = w * 16 + lr;
            int accc = ks * 2 + hc;
            uint32_t aaddr = sb + (uint32_t)(ar * 128 + ((accc << 4) ^ ((ar & 7) << 4)));
            ldsm_x4(ahi, aaddr);
            ldsm_x4(alo, aaddr + dHL);
            #pragma unroll
            for (int nb = 0; nb < 4; nb++) {
                uint32_t kh[4], kl[4];
                int kr = nb * 16 + lr;
                uint32_t kaddr = sb + oK + (uint32_t)(kr * 128 + ((accc << 4) ^ ((kr & 7) << 4)));
                ldsm_x4(kh, kaddr);
                ldsm_x4(kl, kaddr + dHL);
                int j0 = nb * 2, j1 = nb * 2 + 1;
                mma_bf16(sacc[j0], ahi, kh[0], kh[2]);
                mma_bf16(sacc[j1], ahi, kh[1], kh[3]);
                mma_bf16(sacc[j0], ahi, kl[0], kl[2]);
                mma_bf16(sacc[j1], ahi, kl[1], kl[3]);
                mma_bf16(sacc[j0], alo, kh[0], kh[2]);
                mma_bf16(sacc[j1], alo, kh[1], kh[3]);
            }
        }

        // ---- mask + online softmax ----
        float mx0 = -1e30f, mx8 = -1e30f;
        #pragma unroll
        for (int j = 0; j < 8; j++) {
            int k0 = kb + j * 8 + c2;
            float ms0 = maskS[j * 8 + c2], ms1 = maskS[j * 8 + c2 + 1];
            if (k0     > qrow0 || ms0 == 0.f) sacc[j][0] = -1e30f;
            if (k0 + 1 > qrow0 || ms1 == 0.f) sacc[j][1] = -1e30f;
            if (k0     > qrow8 || ms0 == 0.f) sacc[j][2] = -1e30f;
            if (k0 + 1 > qrow8 || ms1 == 0.f) sacc[j][3] = -1e30f;
            mx0 = fmaxf(mx0, fmaxf(sacc[j][0], sacc[j][1]));
            mx8 = fmaxf(mx8, fmaxf(sacc[j][2], sacc[j][3]));
        }
        mx0 = fmaxf(mx0, __shfl_xor_sync(0xffffffffu, mx0, 1));
        mx0 = fmaxf(mx0, __shfl_xor_sync(0xffffffffu, mx0, 2));
        mx8 = fmaxf(mx8, __shfl_xor_sync(0xffffffffu, mx8, 1));
        mx8 = fmaxf(mx8, __shfl_xor_sync(0xffffffffu, mx8, 2));

        float nm0 = fmaxf(m0, mx0), nm8 = fmaxf(m8, mx8);
        float corr0 = __expf(m0 - nm0), corr8 = __expf(m8 - nm8);
        m0 = nm0; m8 = nm8;

        float ps0 = 0.f, ps8 = 0.f;
        #pragma unroll
        for (int j = 0; j < 8; j++) {
            sacc[j][0] = __expf(sacc[j][0] - nm0);
            sacc[j][1] = __expf(sacc[j][1] - nm0);
            sacc[j][2] = __expf(sacc[j][2] - nm8);
            sacc[j][3] = __expf(sacc[j][3] - nm8);
            ps0 += sacc[j][0] + sacc[j][1];
            ps8 += sacc[j][2] + sacc[j][3];
        }
        ps0 += __shfl_xor_sync(0xffffffffu, ps0, 1);
        ps0 += __shfl_xor_sync(0xffffffffu, ps0, 2);
        ps8 += __shfl_xor_sync(0xffffffffu, ps8, 1);
        ps8 += __shfl_xor_sync(0xffffffffu, ps8, 2);
        l0 = l0 * corr0 + ps0;
        l8 = l8 * corr8 + ps8;

        #pragma unroll
        for (int j = 0; j < 8; j++) {
            yacc[j][0] *= corr0; yacc[j][1] *= corr0;
            yacc[j][2] *= corr8; yacc[j][3] *= corr8;
        }

        // ---- Y += P V ----
        #pragma unroll
        for (int kk = 0; kk < 4; kk++) {
            uint32_t phi[4], plo[4];
            pack_split(sacc[kk * 2][0],     sacc[kk * 2][1],     phi[0], plo[0]);
            pack_split(sacc[kk * 2][2],     sacc[kk * 2][3],     phi[1], plo[1]);
            pack_split(sacc[kk * 2 + 1][0], sacc[kk * 2 + 1][1], phi[2], plo[2]);
            pack_split(sacc[kk * 2 + 1][2], sacc[kk * 2 + 1][3], phi[3], plo[3]);
            #pragma unroll
            for (int nb = 0; nb < 4; nb++) {
                uint32_t vh[4], vl[4];
                int vr = kk * 16 + lr;
                int vcc = nb * 2 + hc;
                uint32_t vaddr = sb + oV + (uint32_t)(vr * 128 + ((vcc << 4) ^ ((vr & 7) << 4)));
                ldsm_x4_t(vh, vaddr);
                ldsm_x4_t(vl, vaddr + dHL);
                int j0 = nb * 2, j1 = nb * 2 + 1;
                mma_bf16(yacc[j0], phi, vh[0], vh[1]);
                mma_bf16(yacc[j1], phi, vh[2], vh[3]);
                mma_bf16(yacc[j0], phi, vl[0], vl[1]);
                mma_bf16(yacc[j1], phi, vl[2], vl[3]);
                mma_bf16(yacc[j0], plo, vh[0], vh[1]);
                mma_bf16(yacc[j1], plo, vh[2], vh[3]);
            }
        }
    }

    // ---- normalize + split-bf16 output ----
    float inv0 = 1.0f / l0, inv8 = 1.0f / l8;
    size_t row0 = (bT + qb + w * 16 + g) * P_PROJ + h * HD;
    size_t row8 = row0 + (size_t)8 * P_PROJ;
    #pragma unroll
    for (int j = 0; j < 8; j++) {
        int col = j * 8 + c2;
        split_store2(Yhi, Ylo, row0 + col, yacc[j][0] * inv0, yacc[j][1] * inv0);
        split_store2(Yhi, Ylo, row8 + col, yacc[j][2] * inv8, yacc[j][3] * inv8);
    }
}

// ---------------------------------------------------------------------------
// Host orchestration
// ---------------------------------------------------------------------------
static void split_launch(const float* src, __nv_bfloat16* hi, __nv_bfloat16* lo, int n) {
    int n4 = n / 4;
    split_kernel<<<(n4 + 255) / 256, 256>>>((const float4*)src, hi, lo, n4);
}

extern "C" void kernel_launch(void* const* d_in, const int* in_sizes, int n_in,
                              void* d_out, int out_size)
{
    const int*   idx       = (const int*)  d_in[0];
    const float* attn_mask = (const float*)d_in[1];
    const float* tok_emb   = (const float*)d_in[2];
    const float* pos_emb   = (const float*)d_in[3];
    const float* ln1_g     = (const float*)d_in[4];
    const float* ln1_b     = (const float*)d_in[5];
    const float* Wq        = (const float*)d_in[6];
    const float* bq        = (const float*)d_in[7];
    const float* Wk        = (const float*)d_in[8];
    const float* bk        = (const float*)d_in[9];
    const float* Wv        = (const float*)d_in[10];
    const float* bv        = (const float*)d_in[11];
    const float* Wo        = (const float*)d_in[12];
    const float* bo        = (const float*)d_in[13];
    const float* ln2_g     = (const float*)d_in[14];
    const float* ln2_b     = (const float*)d_in[15];
    const float* W1        = (const float*)d_in[16];
    const float* b1        = (const float*)d_in[17];
    const float* W2        = (const float*)d_in[18];
    const float* b2        = (const float*)d_in[19];
    const float* lnf_g     = (const float*)d_in[20];
    const float* lnf_b     = (const float*)d_in[21];
    const float* W_out     = (const float*)d_in[22];
    float* out = (float*)d_out;

    float *x, *bqkv, *part;
    __nv_bfloat16 *qkv_hi, *qkv_lo;
    __nv_bfloat16 *h_hi, *h_lo, *y_hi, *y_lo, *m1_hi, *m1_lo;
    __nv_bfloat16 *wqkv_hi, *wqkv_lo;
    __nv_bfloat16 *wo_hi, *wo_lo, *w1_hi, *w1_lo, *w2_hi, *w2_lo, *wout_hi, *wout_lo;

    cudaGetSymbolAddress((void**)&x,    g_x);
    cudaGetSymbolAddress((void**)&bqkv, g_bqkv);
    cudaGetSymbolAddress((void**)&part, g_part);
    cudaGetSymbolAddress((void**)&qkv_hi, g_qkv_hi);
    cudaGetSymbolAddress((void**)&qkv_lo, g_qkv_lo);
    cudaGetSymbolAddress((void**)&h_hi,  g_h_hi);
    cudaGetSymbolAddress((void**)&h_lo,  g_h_lo);
    cudaGetSymbolAddress((void**)&y_hi,  g_y_hi);
    cudaGetSymbolAddress((void**)&y_lo,  g_y_lo);
    cudaGetSymbolAddress((void**)&m1_hi, g_m1_hi);
    cudaGetSymbolAddress((void**)&m1_lo, g_m1_lo);
    cudaGetSymbolAddress((void**)&wqkv_hi, g_wqkv_hi);
    cudaGetSymbolAddress((void**)&wqkv_lo, g_wqkv_lo);
    cudaGetSymbolAddress((void**)&wo_hi, g_wo_hi);
    cudaGetSymbolAddress((void**)&wo_lo, g_wo_lo);
    cudaGetSymbolAddress((void**)&w1_hi, g_w1_hi);
    cudaGetSymbolAddress((void**)&w1_lo, g_w1_lo);
    cudaGetSymbolAddress((void**)&w2_hi, g_w2_hi);
    cudaGetSymbolAddress((void**)&w2_lo, g_w2_lo);
    cudaGetSymbolAddress((void**)&wout_hi, g_wout_hi);
    cudaGetSymbolAddress((void**)&wout_lo, g_wout_lo);

    cudaFuncSetAttribute(hgemm_kernel<1>, cudaFuncAttributeMaxDynamicSharedMemorySize, GEMM_SMEM_BYTES);
    cudaFuncSetAttribute(hgemm_kernel<3>, cudaFuncAttributeMaxDynamicSharedMemorySize, GEMM_SMEM_BYTES);
    cudaFuncSetAttribute(hgemm_kernel<4>, cudaFuncAttributeMaxDynamicSharedMemorySize, GEMM_SMEM_BYTES);
    cudaFuncSetAttribute(hgemm_kernel<5>, cudaFuncAttributeMaxDynamicSharedMemorySize, GEMM_SMEM_BYTES);
    cudaFuncSetAttribute(attn_tc_kernel,  cudaFuncAttributeMaxDynamicSharedMemorySize, ATT_SMEM_BYTES);

    const dim3 gqkv (NQKV / BN, ROWS / BM);          // (18, 128)
    const dim3 gsk  (P_PROJ / BN, ROWS / BM, 3);     // split-K x3 -> 2304 CTAs
    const dim3 gff  (FF_DIM / BN, ROWS / BM);        // (24, 128)
    const dim3 ghead(V_VOCAB / BN, ROWS / BM);       // (4, 128)
    const dim3 gattn(T_SEQ / 64, B_BATCH * N_HEADS); // (16, 96)
    const int  npack = (L_LAYERS * D_MODEL * (NQKV / 4) + 255) / 256;

    float* part0 = part;
    float* part1 = part + (size_t)ROWS * D_MODEL;
    float* part2 = part + (size_t)2 * ROWS * D_MODEL;

    // Launch order keeps ncu's sampled launch (index 3) = fused-QKV hgemm.
    embed_kernel<<<ROWS, 256>>>(idx, tok_emb, pos_emb, x);                               // 0
    layernorm_split_kernel<<<ROWS, 256>>>(x, ln1_g, ln1_b, h_hi, h_lo);                  // 1
    pack_qkv_kernel<<<npack, 256>>>(Wq, Wk, Wv, bq, bk, bv, wqkv_hi, wqkv_lo, bqkv);     // 2
    hgemm_kernel<5><<<gqkv, 128, GEMM_SMEM_BYTES>>>(                                     // 3 <- profiled
        h_hi, h_lo, wqkv_hi, wqkv_lo, bqkv,
        nullptr, qkv_hi, qkv_lo, ROWS, NQKV, D_MODEL);
    split_launch(Wo, wo_hi, wo_lo, L_LAYERS * P_PROJ * D_MODEL);                         // 4
    split_launch(W1, w1_hi, w1_lo, L_LAYERS * D_MODEL * FF_DIM);                         // 5
    split_launch(W2, w2_hi, w2_lo, L_LAYERS * FF_DIM * D_MODEL);                         // 6
    split_launch(W_out, wout_hi, wout_lo, D_MODEL * V_VOCAB);                            // 7

    for (int l = 0; l < L_LAYERS; l++) {
        const size_t wqkvo = (size_t)l * D_MODEL * NQKV;
        const size_t wdp   = (size_t)l * D_MODEL * P_PROJ;
        const size_t wdf   = (size_t)l * D_MODEL * FF_DIM;

        attn_tc_kernel<<<gattn, 128, ATT_SMEM_BYTES>>>(qkv_hi, qkv_lo, attn_mask, y_hi, y_lo);

        // part = y @ Wo (split-K x3); fused: x += part* + bo, h = LN2(x)
        hgemm_kernel<4><<<gsk, 128, GEMM_SMEM_BYTES>>>(
            y_hi, y_lo, wo_hi + wdp, wo_lo + wdp, nullptr,
            part, nullptr, nullptr, ROWS, D_MODEL, P_PROJ);
        ln_residual_split_kernel<<<ROWS, 256>>>(
            x, part0, part1, part2, bo + l * D_MODEL,
            ln2_g + l * D_MODEL, ln2_b + l * D_MODEL, h_hi, h_lo);

        // m1 = gelu(h @ W1 + b1) -> split bf16
        hgemm_kernel<1><<<gff, 128, GEMM_SMEM_BYTES>>>(
            h_hi, h_lo, w1_hi + wdf, w1_lo + wdf, b1 + l * FF_DIM,
            nullptr, m1_hi, m1_lo, ROWS, FF_DIM, D_MODEL);
        // part = m1 @ W2 (split-K x3); fused residual + next LN
        hgemm_kernel<4><<<gsk, 128, GEMM_SMEM_BYTES>>>(
            m1_hi, m1_lo, w2_hi + wdf, w2_lo + wdf, nullptr,
            part, nullptr, nullptr, ROWS, D_MODEL, FF_DIM);

        if (l + 1 < L_LAYERS) {
            ln_residual_split_kernel<<<ROWS, 256>>>(
                x, part0, part1, part2, b2 + l * D_MODEL,
                ln1_g + (l + 1) * D_MODEL, ln1_b + (l + 1) * D_MODEL, h_hi, h_lo);
            hgemm_kernel<5><<<gqkv, 128, GEMM_SMEM_BYTES>>>(
                h_hi, h_lo, wqkv_hi + wqkvo + (size_t)D_MODEL * NQKV,
                wqkv_lo + wqkvo + (size_t)D_MODEL * NQKV, bqkv + (l + 1) * NQKV,
                nullptr, qkv_hi, qkv_lo, ROWS, NQKV, D_MODEL);
        } else {
            ln_residual_split_kernel<<<ROWS, 256>>>(
                x, part0, part1, part2, b2 + l * D_MODEL,
                lnf_g, lnf_b, h_hi, h_lo);
        }
    }

    hgemm_kernel<3><<<ghead, 128, GEMM_SMEM_BYTES>>>(
        h_hi, h_lo, wout_hi, wout_lo, nullptr,
        out, nullptr, nullptr, ROWS, V_VOCAB, D_MODEL);
}